// round 10
// baseline (speedup 1.0000x reference)
#include <cuda_runtime.h>
#include <cuda_bf16.h>
#include <cstdint>

#define B_   2
#define N_   2048
#define DIM_ 1024
#define H_   16
#define D_   64
#define BH_  (B_ * H_)
#define M_   (B_ * N_)

// ---- device scratch (allocation-free rule) ----
__device__ __nv_bfloat16 g_fh[(size_t)M_ * DIM_];
__device__ __nv_bfloat16 g_fl[(size_t)M_ * DIM_];
__device__ __nv_bfloat16 g_wqh[(size_t)3 * DIM_ * DIM_];
__device__ __nv_bfloat16 g_wql[(size_t)3 * DIM_ * DIM_];
__device__ __nv_bfloat16 g_woh[(size_t)DIM_ * DIM_];
__device__ __nv_bfloat16 g_wol[(size_t)DIM_ * DIM_];
__device__ __nv_bfloat16 g_qh[(size_t)BH_ * N_ * D_];
__device__ __nv_bfloat16 g_ql[(size_t)BH_ * N_ * D_];
__device__ __nv_bfloat16 g_kh[(size_t)BH_ * N_ * D_];
__device__ __nv_bfloat16 g_kl[(size_t)BH_ * N_ * D_];
__device__ __nv_bfloat16 g_vh[(size_t)BH_ * D_ * N_];
__device__ __nv_bfloat16 g_vl[(size_t)BH_ * D_ * N_];
__device__ __nv_bfloat16 g_ah[(size_t)M_ * DIM_];
__device__ __nv_bfloat16 g_al[(size_t)M_ * DIM_];
__device__ float g_e[(size_t)BH_ * N_ * N_];   // exp(scores), warp-private f4 layout

__device__ __forceinline__ unsigned b2u(__nv_bfloat162 v) {
    return *reinterpret_cast<unsigned*>(&v);
}
__device__ __forceinline__ void split2(float x0, float x1, unsigned& hi, unsigned& lo) {
    __nv_bfloat162 h2 = __floats2bfloat162_rn(x0, x1);
    __nv_bfloat162 l2 = __floats2bfloat162_rn(x0 - __bfloat162float(h2.x),
                                              x1 - __bfloat162float(h2.y));
    hi = b2u(h2); lo = b2u(l2);
}

__device__ __forceinline__ void mma16816(float* c, unsigned a0, unsigned a1,
                                         unsigned a2, unsigned a3,
                                         unsigned b0, unsigned b1) {
    asm("mma.sync.aligned.m16n8k16.row.col.f32.bf16.bf16.f32 "
        "{%0,%1,%2,%3},{%4,%5,%6,%7},{%8,%9},{%0,%1,%2,%3};\n"
        : "+f"(c[0]), "+f"(c[1]), "+f"(c[2]), "+f"(c[3])
        : "r"(a0), "r"(a1), "r"(a2), "r"(a3), "r"(b0), "r"(b1));
}

__device__ __forceinline__ void ldsm4(unsigned addr, unsigned& r0, unsigned& r1,
                                      unsigned& r2, unsigned& r3) {
    asm volatile("ldmatrix.sync.aligned.m8n8.x4.shared.b16 {%0,%1,%2,%3}, [%4];\n"
                 : "=r"(r0), "=r"(r1), "=r"(r2), "=r"(r3) : "r"(addr));
}

__device__ __forceinline__ void cpa16(unsigned dst, const void* src) {
    asm volatile("cp.async.cg.shared.global [%0], [%1], 16;\n" :: "r"(dst), "l"(src));
}
__device__ __forceinline__ void cp_commit() { asm volatile("cp.async.commit_group;\n"); }
__device__ __forceinline__ void cp_wait1() { asm volatile("cp.async.wait_group 1;\n"); }
__device__ __forceinline__ void cp_wait0() { asm volatile("cp.async.wait_group 0;\n"); }

// ---------------------------------------------------------------------------
// m64 x n32 x k64 warp-tile block-MMA, hi/lo split (3 products), stride 36 w.
// A rows arow..arow+63, B(n) rows bcol..bcol+31. c[mt*4+nt][4].
// ---------------------------------------------------------------------------
__device__ __forceinline__ void mma_tile64(unsigned sb, int AH, int AL,
                                           int BHo, int BLo, int arow, int bcol,
                                           int lane, float c[16][4]) {
    const int m = lane >> 3, r = lane & 7;
    const unsigned paw = (unsigned)((arow + (m & 1) * 8 + r) * 36 + (m >> 1) * 4) * 4;
    const unsigned pbw = (unsigned)((bcol + (m >> 1) * 8 + r) * 36 + (m & 1) * 4) * 4;
#pragma unroll
    for (int ks = 0; ks < 4; ks++) {
        unsigned ah[4][4], al_[4][4];
#pragma unroll
        for (int mt = 0; mt < 4; mt++) {
            ldsm4(sb + AH * 4 + paw + mt * (16 * 36 * 4) + ks * 32,
                  ah[mt][0], ah[mt][1], ah[mt][2], ah[mt][3]);
            ldsm4(sb + AL * 4 + paw + mt * (16 * 36 * 4) + ks * 32,
                  al_[mt][0], al_[mt][1], al_[mt][2], al_[mt][3]);
        }
#pragma unroll
        for (int np = 0; np < 2; np++) {
            unsigned bh[4], bl[4];
            ldsm4(sb + BHo * 4 + pbw + np * (16 * 36 * 4) + ks * 32,
                  bh[0], bh[1], bh[2], bh[3]);
            ldsm4(sb + BLo * 4 + pbw + np * (16 * 36 * 4) + ks * 32,
                  bl[0], bl[1], bl[2], bl[3]);
#pragma unroll
            for (int mt = 0; mt < 4; mt++) {
                float* c0 = c[mt * 4 + np * 2 + 0];
                float* c1 = c[mt * 4 + np * 2 + 1];
                mma16816(c0, ah[mt][0], ah[mt][1], ah[mt][2], ah[mt][3], bh[0], bh[1]);
                mma16816(c0, ah[mt][0], ah[mt][1], ah[mt][2], ah[mt][3], bl[0], bl[1]);
                mma16816(c0, al_[mt][0], al_[mt][1], al_[mt][2], al_[mt][3], bh[0], bh[1]);
                mma16816(c1, ah[mt][0], ah[mt][1], ah[mt][2], ah[mt][3], bh[2], bh[3]);
                mma16816(c1, ah[mt][0], ah[mt][1], ah[mt][2], ah[mt][3], bl[2], bl[3]);
                mma16816(c1, al_[mt][0], al_[mt][1], al_[mt][2], al_[mt][3], bh[2], bh[3]);
            }
        }
    }
}

// ---------------- preprocess: splits ----------------
__global__ __launch_bounds__(256) void split_f32(const float* __restrict__ src,
                                                 __nv_bfloat16* __restrict__ dh,
                                                 __nv_bfloat16* __restrict__ dl,
                                                 int n2) {
    int i = blockIdx.x * 256 + threadIdx.x;
    if (i < n2) {
        float2 v = reinterpret_cast<const float2*>(src)[i];
        unsigned hi, lo; split2(v.x, v.y, hi, lo);
        reinterpret_cast<unsigned*>(dh)[i] = hi;
        reinterpret_cast<unsigned*>(dl)[i] = lo;
    }
}

__global__ __launch_bounds__(256) void tsplit_w(const float* __restrict__ W,
                                                __nv_bfloat16* __restrict__ dh,
                                                __nv_bfloat16* __restrict__ dl,
                                                int K, int NB) {
    __shared__ float tile[32][33];
    const int n0 = blockIdx.x * 32, k0 = blockIdx.y * 32;
    const int tx = threadIdx.x & 31, ty = threadIdx.x >> 5;
    for (int r = ty; r < 32; r += 8)
        tile[r][tx] = W[(size_t)(k0 + r) * NB + n0 + tx];
    __syncthreads();
    for (int u = threadIdx.x; u < 512; u += 256) {
        const int rr = u >> 4, c = (u & 15) * 2;
        unsigned hi, lo; split2(tile[c][rr], tile[c + 1][rr], hi, lo);
        const size_t off = ((size_t)(n0 + rr) * K + k0 + c) >> 1;
        reinterpret_cast<unsigned*>(dh)[off] = hi;
        reinterpret_cast<unsigned*>(dl)[off] = lo;
    }
}

// ---------------- HMMA GEMM: 128m x 64n, 4 warps @ 64x32, 2-stage ----------
#define SAH 0
#define SAL 4608
#define SBH 9216
#define SBL 11520
#define GSTG 13824

__global__ __launch_bounds__(128, 2) void mma_gemm(
    const __nv_bfloat16* __restrict__ Ah, const __nv_bfloat16* __restrict__ Al,
    const __nv_bfloat16* __restrict__ Bh, const __nv_bfloat16* __restrict__ Bl,
    float* __restrict__ Cout, int mode) {
    extern __shared__ unsigned su[];
    const unsigned sbase = (unsigned)__cvta_generic_to_shared(su);
    const int K = 1024;
    const int m0 = blockIdx.y * 128, n0 = blockIdx.x * 64;
    const int tid = threadIdx.x, lane = tid & 31, wp = tid >> 5;
    const int g = lane >> 2, t = lane & 3;
    const int rg = (wp >> 1) * 64, cg = wp & 1;

    const uint4* pAh = reinterpret_cast<const uint4*>(Ah + (size_t)m0 * K);
    const uint4* pAl = reinterpret_cast<const uint4*>(Al + (size_t)m0 * K);
    const uint4* pBh = reinterpret_cast<const uint4*>(Bh + (size_t)n0 * K);
    const uint4* pBl = reinterpret_cast<const uint4*>(Bl + (size_t)n0 * K);

    float c16[16][4] = {};

#define GLOAD(ST, K0)                                                          \
    {                                                                          \
        const int kc = (K0) >> 3;                                              \
        const unsigned base = sbase + (ST) * (GSTG * 4);                       \
        for (int idx = tid; idx < 2048; idx += 128) {                          \
            const int half = idx >> 10, r = (idx & 1023) >> 3, c = idx & 7;    \
            cpa16(base + (half ? SAL : SAH) * 4 + (r * 9 + c) * 16,            \
                  (half ? pAl : pAh) + (size_t)r * 128 + kc + c);              \
        }                                                                      \
        for (int idx = tid; idx < 1024; idx += 128) {                          \
            const int half = idx >> 9, r = (idx & 511) >> 3, c = idx & 7;      \
            cpa16(base + (half ? SBL : SBH) * 4 + (r * 9 + c) * 16,            \
                  (half ? pBl : pBh) + (size_t)r * 128 + kc + c);              \
        }                                                                      \
        cp_commit();                                                           \
    }

    GLOAD(0, 0)
    for (int it = 0; it < 16; it++) {
        if (it + 1 < 16) { GLOAD((it + 1) & 1, (it + 1) * 64) cp_wait1(); }
        else cp_wait0();
        __syncthreads();
        mma_tile64(sbase + (it & 1) * (GSTG * 4), SAH, SAL, SBH, SBL,
                   rg, cg * 32, lane, c16);
        __syncthreads();
    }
#undef GLOAD

    if (mode == 0) {
        const int part = n0 >> 10;
        const int b = m0 >> 11;
        const int mloc = m0 & (N_ - 1);
        const int hh = (n0 & 1023) >> 6;
        const int bh = b * H_ + hh;
        if (part < 2) {
            const float SCp = (part == 0) ? 0.03125f : 1.0f;
            unsigned* uh = reinterpret_cast<unsigned*>(part == 0 ? g_qh : g_kh);
            unsigned* ul = reinterpret_cast<unsigned*>(part == 0 ? g_ql : g_kl);
#pragma unroll
            for (int mt = 0; mt < 4; mt++)
#pragma unroll
                for (int nt = 0; nt < 4; nt++) {
                    const float* cc = c16[mt * 4 + nt];
                    const int R0 = mloc + rg + mt * 16 + g;
                    const int d = cg * 32 + nt * 8 + 2 * t;
                    unsigned hi, lo;
                    split2(cc[0] * SCp, cc[1] * SCp, hi, lo);
                    const size_t o0 = (((size_t)bh * N_ + R0) * D_ + d) >> 1;
                    uh[o0] = hi; ul[o0] = lo;
                    split2(cc[2] * SCp, cc[3] * SCp, hi, lo);
                    const size_t o1 = (((size_t)bh * N_ + R0 + 8) * D_ + d) >> 1;
                    uh[o1] = hi; ul[o1] = lo;
                }
        } else {
#pragma unroll
            for (int mt = 0; mt < 4; mt++)
#pragma unroll
                for (int nt = 0; nt < 4; nt++) {
                    const float* cc = c16[mt * 4 + nt];
                    const int i0v = mloc + rg + mt * 16 + g;
                    const int d = cg * 32 + nt * 8 + 2 * t;
                    const size_t b0 = ((size_t)bh * D_ + d) * N_;
                    const size_t b1 = ((size_t)bh * D_ + d + 1) * N_;
#pragma unroll
                    for (int q = 0; q < 4; q++) {
                        const float v = cc[q];
                        const size_t off = ((q & 1) ? b1 : b0) + i0v + (q >> 1) * 8;
                        const __nv_bfloat16 hb = __float2bfloat16(v);
                        g_vh[off] = hb;
                        g_vl[off] = __float2bfloat16(v - __bfloat162float(hb));
                    }
                }
        }
    } else {
#pragma unroll
        for (int mt = 0; mt < 4; mt++)
#pragma unroll
            for (int nt = 0; nt < 4; nt++) {
                const float* cc = c16[mt * 4 + nt];
                const int R0 = m0 + rg + mt * 16 + g;
                const int n = n0 + cg * 32 + nt * 8 + 2 * t;
                *reinterpret_cast<float2*>(&Cout[(size_t)R0 * DIM_ + n]) =
                    make_float2(cc[0], cc[1]);
                *reinterpret_cast<float2*>(&Cout[(size_t)(R0 + 8) * DIM_ + n]) =
                    make_float2(cc[2], cc[3]);
            }
    }
}

// ---------------- HMMA segment attention: 128 rows, 4 warps @ 64x32 ---------
// smem words: QH/WH 0, QL/WL 4608; stages 9216 + s*4608 (XH+0, XL+2304);
// dsh/inv 18432 (512 f). total 18944 w = 75776 B -> 3 blocks/SM
#define SQH 0
#define SQL 4608
#define ASST 9216
#define ASDS 18432

#define ACCSEG(DS, SG, E)                                                      \
    { if ((SG) == 0) (DS)[0] += (E); else if ((SG) == 1) (DS)[1] += (E);       \
      else if ((SG) == 2) (DS)[2] += (E); else (DS)[3] += (E); }

__global__ __launch_bounds__(128, 3) void attn_mma(const int* __restrict__ mask) {
    extern __shared__ unsigned su[];
    const unsigned sbase = (unsigned)__cvta_generic_to_shared(su);
    float* dshf = reinterpret_cast<float*>(su + ASDS);
    uint4* su4 = reinterpret_cast<uint4*>(su);

    const int b = blockIdx.z, h = blockIdx.x;
    const int i0 = blockIdx.y * 128;
    const int bh = b * H_ + h;
    const int tid = threadIdx.x;
    const int lane = tid & 31, wp = tid >> 5;
    const int g = lane >> 2, t = lane & 3;
    const int rg = (wp >> 1) * 64, cg = wp & 1;
    const int* mrow = mask + (size_t)b * N_ * N_ + (size_t)i0 * N_;
    float* eblk = g_e + (((size_t)bh * 16 + blockIdx.y) << 18);

    // load Q tile (hi/lo), zero dsh
    {
        const uint4* gqh = reinterpret_cast<const uint4*>(g_qh + ((size_t)bh * N_ + i0) * D_);
        const uint4* gql = reinterpret_cast<const uint4*>(g_ql + ((size_t)bh * N_ + i0) * D_);
        for (int idx = tid; idx < 2048; idx += 128) {
            const int half = idx >> 10, r = (idx & 1023) >> 3, c = idx & 7;
            su4[((half ? SQL : SQH) >> 2) + r * 9 + c] = (half ? gql : gqh)[r * 8 + c];
        }
        for (int idx = tid; idx < 512; idx += 128) dshf[idx] = 0.0f;
    }

    const uint4* gkh = reinterpret_cast<const uint4*>(g_kh + (size_t)bh * N_ * D_);
    const uint4* gkl = reinterpret_cast<const uint4*>(g_kl + (size_t)bh * N_ * D_);
    const uint4* gvh = reinterpret_cast<const uint4*>(g_vh + (size_t)bh * D_ * N_);
    const uint4* gvl = reinterpret_cast<const uint4*>(g_vl + (size_t)bh * D_ * N_);

#define LOADK(ST, JT)                                                          \
    {                                                                          \
        const unsigned base = sbase + (ASST + (ST) * 4608) * 4;                \
        const int jr = (JT) * 512;                                             \
        for (int idx = tid; idx < 1024; idx += 128) {                          \
            const int half = idx >> 9, r = (idx & 511) >> 3, c = idx & 7;      \
            cpa16(base + half * 9216 + (r * 9 + c) * 16,                       \
                  (half ? gkl : gkh) + jr + (size_t)r * 8 + c);                \
        }                                                                      \
        cp_commit();                                                           \
    }
#define LOADV(ST, JT)                                                          \
    {                                                                          \
        const unsigned base = sbase + (ASST + (ST) * 4608) * 4;                \
        const int jc = (JT) * 8;                                               \
        for (int idx = tid; idx < 1024; idx += 128) {                          \
            const int half = idx >> 9, r = (idx & 511) >> 3, c = idx & 7;      \
            cpa16(base + half * 9216 + (r * 9 + c) * 16,                       \
                  (half ? gvl : gvh) + (size_t)r * 256 + jc + c);              \
        }                                                                      \
        cp_commit();                                                           \
    }

    // ---------------- PASS 1: denominators + e store ----------------
    float ds[8][4] = {};
    LOADK(0, 0)
    for (int jt = 0; jt < 32; jt++) {
        if (jt + 1 < 32) { LOADK((jt + 1) & 1, jt + 1) cp_wait1(); }
        else cp_wait0();
        __syncthreads();
        const int koff = ASST + (jt & 1) * 4608;
        float c16[16][4] = {};
        mma_tile64(sbase, SQH, SQL, koff, koff + 2304, rg, cg * 32, lane, c16);
        __syncthreads();
        float4* ew4 = reinterpret_cast<float4*>(eblk + ((size_t)jt * 4 + wp) * 2048);
        const int j0 = jt * 64;
#pragma unroll
        for (int mt = 0; mt < 4; mt++)
#pragma unroll
            for (int nt = 0; nt < 4; nt++) {
                const float* cc = c16[mt * 4 + nt];
                const int R0 = rg + mt * 16 + g;
                const int j = j0 + cg * 32 + nt * 8 + 2 * t;
                const int2 ma = *reinterpret_cast<const int2*>(&mrow[(size_t)R0 * N_ + j]);
                const int2 mb = *reinterpret_cast<const int2*>(&mrow[(size_t)(R0 + 8) * N_ + j]);
                const float e0 = __expf(cc[0]), e1 = __expf(cc[1]);
                const float e2 = __expf(cc[2]), e3 = __expf(cc[3]);
                ACCSEG(ds[mt * 2], ma.x, e0) ACCSEG(ds[mt * 2], ma.y, e1)
                ACCSEG(ds[mt * 2 + 1], mb.x, e2) ACCSEG(ds[mt * 2 + 1], mb.y, e3)
                ew4[(mt * 4 + nt) * 32 + lane] = make_float4(e0, e1, e2, e3);
            }
    }
#pragma unroll
    for (int slot = 0; slot < 8; slot++)
#pragma unroll
        for (int s = 0; s < 4; s++) {
            float v = ds[slot][s];
            v += __shfl_xor_sync(0xffffffffu, v, 1);
            v += __shfl_xor_sync(0xffffffffu, v, 2);
            if (t == 0)
                atomicAdd(&dshf[(rg + (slot >> 1) * 16 + (slot & 1) * 8 + g) * 4 + s], v);
        }
    __syncthreads();
    for (int idx = tid; idx < 512; idx += 128) {
        const float dv = dshf[idx];
        dshf[idx] = (dv == 0.0f) ? 1.0f : 1.0f / dv;
    }
    __syncthreads();

    // ---------------- PASS 2: w = e*invd -> O += w @ V ----------------
    float o16[16][4] = {};
    LOADV(0, 0)
    for (int jt = 0; jt < 32; jt++) {
        if (jt + 1 < 32) LOADV((jt + 1) & 1, jt + 1)
        const float4* ew4 =
            reinterpret_cast<const float4*>(eblk + ((size_t)jt * 4 + wp) * 2048);
        const int j0 = jt * 64;
#pragma unroll
        for (int mt = 0; mt < 4; mt++)
#pragma unroll
            for (int nt = 0; nt < 4; nt++) {
                const float4 f4 = ew4[(mt * 4 + nt) * 32 + lane];
                const int R0 = rg + mt * 16 + g;
                const int j = j0 + cg * 32 + nt * 8 + 2 * t;
                const int2 ma = *reinterpret_cast<const int2*>(&mrow[(size_t)R0 * N_ + j]);
                const int2 mb = *reinterpret_cast<const int2*>(&mrow[(size_t)(R0 + 8) * N_ + j]);
                const float w00 = f4.x * dshf[R0 * 4 + ma.x];
                const float w01 = f4.y * dshf[R0 * 4 + ma.y];
                const float w10 = f4.z * dshf[(R0 + 8) * 4 + mb.x];
                const float w11 = f4.w * dshf[(R0 + 8) * 4 + mb.y];
                const int wc = cg * 16 + nt * 4 + t;
                unsigned hi, lo;
                split2(w00, w01, hi, lo);
                su[SQH + R0 * 36 + wc] = hi;
                su[SQL + R0 * 36 + wc] = lo;
                split2(w10, w11, hi, lo);
                su[SQH + (R0 + 8) * 36 + wc] = hi;
                su[SQL + (R0 + 8) * 36 + wc] = lo;
            }
        if (jt + 1 < 32) cp_wait1(); else cp_wait0();
        __syncthreads();
        const int voff = ASST + (jt & 1) * 4608;
        mma_tile64(sbase, SQH, SQL, voff, voff + 2304, rg, cg * 32, lane, o16);
        __syncthreads();
    }
#undef LOADK
#undef LOADV

    // store O as split bf16
    {
        unsigned* ah = reinterpret_cast<unsigned*>(g_ah);
        unsigned* al = reinterpret_cast<unsigned*>(g_al);
#pragma unroll
        for (int mt = 0; mt < 4; mt++)
#pragma unroll
            for (int nt = 0; nt < 4; nt++) {
                const float* oo = o16[mt * 4 + nt];
                const int R0 = rg + mt * 16 + g;
                const int d = h * 64 + cg * 32 + nt * 8 + 2 * t;
                unsigned hi, lo;
                split2(oo[0], oo[1], hi, lo);
                const size_t o0 = ((size_t)(b * N_ + i0 + R0) * DIM_ + d) >> 1;
                ah[o0] = hi; al[o0] = lo;
                split2(oo[2], oo[3], hi, lo);
                const size_t o1 = ((size_t)(b * N_ + i0 + R0 + 8) * DIM_ + d) >> 1;
                ah[o1] = hi; al[o1] = lo;
            }
    }
}

// ---------------------------------------------------------------------------
extern "C" void kernel_launch(void* const* d_in, const int* in_sizes, int n_in,
                              void* d_out, int out_size) {
    const float* features = (const float*)d_in[0];
    const int*   mask     = (const int*)d_in[1];
    const float* W_qkv    = (const float*)d_in[2];
    const float* W_out    = (const float*)d_in[3];
    float* out = (float*)d_out;

    cudaFuncSetAttribute(attn_mma, cudaFuncAttributeMaxDynamicSharedMemorySize, 75776);
    cudaFuncSetAttribute(mma_gemm, cudaFuncAttributeMaxDynamicSharedMemorySize, 110592);

    __nv_bfloat16 *fh, *fl, *wqh, *wql, *woh, *wol, *ah, *al;
    cudaGetSymbolAddress((void**)&fh, g_fh);   cudaGetSymbolAddress((void**)&fl, g_fl);
    cudaGetSymbolAddress((void**)&wqh, g_wqh); cudaGetSymbolAddress((void**)&wql, g_wql);
    cudaGetSymbolAddress((void**)&woh, g_woh); cudaGetSymbolAddress((void**)&wol, g_wol);
    cudaGetSymbolAddress((void**)&ah, g_ah);   cudaGetSymbolAddress((void**)&al, g_al);

    split_f32<<<(M_ * DIM_ / 2 + 255) / 256, 256>>>(features, fh, fl, M_ * DIM_ / 2);
    tsplit_w<<<dim3(3 * DIM_ / 32, DIM_ / 32), 256>>>(W_qkv, wqh, wql, DIM_, 3 * DIM_);
    tsplit_w<<<dim3(DIM_ / 32, DIM_ / 32), 256>>>(W_out, woh, wol, DIM_, DIM_);

    mma_gemm<<<dim3(3 * DIM_ / 64, M_ / 128), 128, 110592>>>(fh, fl, wqh, wql, nullptr, 0);
    attn_mma<<<dim3(H_, N_ / 128, B_), 128, 75776>>>(mask);
    mma_gemm<<<dim3(DIM_ / 64, M_ / 128), 128, 110592>>>(ah, al, woh, wol, out, 1);
}

// round 11
// speedup vs baseline: 1.3573x; 1.3573x over previous
#include <cuda_runtime.h>
#include <cuda_bf16.h>
#include <cstdint>

#define B_   2
#define N_   2048
#define DIM_ 1024
#define H_   16
#define D_   64
#define BH_  (B_ * H_)
#define M_   (B_ * N_)

// ---- device scratch (allocation-free rule) ----
__device__ __nv_bfloat16 g_fh[(size_t)M_ * DIM_];
__device__ __nv_bfloat16 g_fl[(size_t)M_ * DIM_];
__device__ __nv_bfloat16 g_wqh[(size_t)3 * DIM_ * DIM_];
__device__ __nv_bfloat16 g_wql[(size_t)3 * DIM_ * DIM_];
__device__ __nv_bfloat16 g_woh[(size_t)DIM_ * DIM_];
__device__ __nv_bfloat16 g_wol[(size_t)DIM_ * DIM_];
__device__ __nv_bfloat16 g_qh[(size_t)BH_ * N_ * D_];
__device__ __nv_bfloat16 g_ql[(size_t)BH_ * N_ * D_];
__device__ __nv_bfloat16 g_kh[(size_t)BH_ * N_ * D_];
__device__ __nv_bfloat16 g_kl[(size_t)BH_ * N_ * D_];
__device__ __nv_bfloat16 g_vh[(size_t)BH_ * D_ * N_];
__device__ __nv_bfloat16 g_vl[(size_t)BH_ * D_ * N_];
__device__ __nv_bfloat16 g_ah[(size_t)M_ * DIM_];
__device__ __nv_bfloat16 g_al[(size_t)M_ * DIM_];
__device__ float g_e[(size_t)BH_ * N_ * N_];           // exp(scores), warp-packed

__device__ __forceinline__ unsigned b2u(__nv_bfloat162 v) {
    return *reinterpret_cast<unsigned*>(&v);
}
__device__ __forceinline__ void split2(float x0, float x1, unsigned& hi, unsigned& lo) {
    __nv_bfloat162 h2 = __floats2bfloat162_rn(x0, x1);
    __nv_bfloat162 l2 = __floats2bfloat162_rn(x0 - __bfloat162float(h2.x),
                                              x1 - __bfloat162float(h2.y));
    hi = b2u(h2); lo = b2u(l2);
}

__device__ __forceinline__ void mma16816(float* c, unsigned a0, unsigned a1,
                                         unsigned a2, unsigned a3,
                                         unsigned b0, unsigned b1) {
    asm("mma.sync.aligned.m16n8k16.row.col.f32.bf16.bf16.f32 "
        "{%0,%1,%2,%3},{%4,%5,%6,%7},{%8,%9},{%0,%1,%2,%3};\n"
        : "+f"(c[0]), "+f"(c[1]), "+f"(c[2]), "+f"(c[3])
        : "r"(a0), "r"(a1), "r"(a2), "r"(a3), "r"(b0), "r"(b1));
}

__device__ __forceinline__ void ldsm4(unsigned addr, unsigned& r0, unsigned& r1,
                                      unsigned& r2, unsigned& r3) {
    asm volatile("ldmatrix.sync.aligned.m8n8.x4.shared.b16 {%0,%1,%2,%3}, [%4];\n"
                 : "=r"(r0), "=r"(r1), "=r"(r2), "=r"(r3) : "r"(addr));
}

__device__ __forceinline__ void cpa16(unsigned dst, const void* src) {
    asm volatile("cp.async.cg.shared.global [%0], [%1], 16;\n" :: "r"(dst), "l"(src));
}
__device__ __forceinline__ void cp_commit() { asm volatile("cp.async.commit_group;\n"); }
__device__ __forceinline__ void cp_wait1() { asm volatile("cp.async.wait_group 1;\n"); }
__device__ __forceinline__ void cp_wait0() { asm volatile("cp.async.wait_group 0;\n"); }

// ---------------------------------------------------------------------------
// m64 x n32 x k64 warp-tile block-MMA (GEMM), hi/lo split, stride 36 words.
// ---------------------------------------------------------------------------
__device__ __forceinline__ void mma_tile64(unsigned sb, int AH, int AL,
                                           int BHo, int BLo, int arow, int bcol,
                                           int lane, float c[16][4]) {
    const int m = lane >> 3, r = lane & 7;
    const unsigned paw = (unsigned)((arow + (m & 1) * 8 + r) * 36 + (m >> 1) * 4) * 4;
    const unsigned pbw = (unsigned)((bcol + (m >> 1) * 8 + r) * 36 + (m & 1) * 4) * 4;
#pragma unroll
    for (int ks = 0; ks < 4; ks++) {
        unsigned ah[4][4], al_[4][4];
#pragma unroll
        for (int mt = 0; mt < 4; mt++) {
            ldsm4(sb + AH * 4 + paw + mt * (16 * 36 * 4) + ks * 32,
                  ah[mt][0], ah[mt][1], ah[mt][2], ah[mt][3]);
            ldsm4(sb + AL * 4 + paw + mt * (16 * 36 * 4) + ks * 32,
                  al_[mt][0], al_[mt][1], al_[mt][2], al_[mt][3]);
        }
#pragma unroll
        for (int np = 0; np < 2; np++) {
            unsigned bh[4], bl[4];
            ldsm4(sb + BHo * 4 + pbw + np * (16 * 36 * 4) + ks * 32,
                  bh[0], bh[1], bh[2], bh[3]);
            ldsm4(sb + BLo * 4 + pbw + np * (16 * 36 * 4) + ks * 32,
                  bl[0], bl[1], bl[2], bl[3]);
#pragma unroll
            for (int mt = 0; mt < 4; mt++) {
                float* c0 = c[mt * 4 + np * 2 + 0];
                float* c1 = c[mt * 4 + np * 2 + 1];
                mma16816(c0, ah[mt][0], ah[mt][1], ah[mt][2], ah[mt][3], bh[0], bh[1]);
                mma16816(c0, ah[mt][0], ah[mt][1], ah[mt][2], ah[mt][3], bl[0], bl[1]);
                mma16816(c0, al_[mt][0], al_[mt][1], al_[mt][2], al_[mt][3], bh[0], bh[1]);
                mma16816(c1, ah[mt][0], ah[mt][1], ah[mt][2], ah[mt][3], bh[2], bh[3]);
                mma16816(c1, ah[mt][0], ah[mt][1], ah[mt][2], ah[mt][3], bl[2], bl[3]);
                mma16816(c1, al_[mt][0], al_[mt][1], al_[mt][2], al_[mt][3], bh[2], bh[3]);
            }
        }
    }
}

// m16 x n64 x k64 warp-tile (attention), hi/lo split, stride 36 words.
__device__ __forceinline__ void mma_tile(unsigned sb, int AH, int AL,
                                         int BHo, int BLo, int arow, int lane,
                                         float c[8][4]) {
    const int m = lane >> 3, r = lane & 7;
    const unsigned pa = ((unsigned)(arow + (m & 1) * 8 + r) * 36 + (m >> 1) * 4) * 4;
    const unsigned pb = (((unsigned)((m >> 1) * 8 + r)) * 36 + (m & 1) * 4) * 4;
#pragma unroll
    for (int ks = 0; ks < 4; ks++) {
        unsigned ah0, ah1, ah2, ah3, al0, al1, al2, al3;
        ldsm4(sb + AH * 4 + pa + ks * 32, ah0, ah1, ah2, ah3);
        ldsm4(sb + AL * 4 + pa + ks * 32, al0, al1, al2, al3);
#pragma unroll
        for (int ntp = 0; ntp < 4; ntp++) {
            unsigned bh0, bh1, bh2, bh3, bl0, bl1, bl2, bl3;
            const unsigned bofs = pb + ntp * (16 * 36 * 4) + ks * 32;
            ldsm4(sb + BHo * 4 + bofs, bh0, bh1, bh2, bh3);
            ldsm4(sb + BLo * 4 + bofs, bl0, bl1, bl2, bl3);
            mma16816(c[2 * ntp + 0], ah0, ah1, ah2, ah3, bh0, bh1);
            mma16816(c[2 * ntp + 0], ah0, ah1, ah2, ah3, bl0, bl1);
            mma16816(c[2 * ntp + 0], al0, al1, al2, al3, bh0, bh1);
            mma16816(c[2 * ntp + 1], ah0, ah1, ah2, ah3, bh2, bh3);
            mma16816(c[2 * ntp + 1], ah0, ah1, ah2, ah3, bl2, bl3);
            mma16816(c[2 * ntp + 1], al0, al1, al2, al3, bh2, bh3);
        }
    }
}

// ---------------- preprocess: splits ----------------
__global__ __launch_bounds__(256) void split_f32(const float* __restrict__ src,
                                                 __nv_bfloat16* __restrict__ dh,
                                                 __nv_bfloat16* __restrict__ dl,
                                                 int n2) {
    int i = blockIdx.x * 256 + threadIdx.x;
    if (i < n2) {
        float2 v = reinterpret_cast<const float2*>(src)[i];
        unsigned hi, lo; split2(v.x, v.y, hi, lo);
        reinterpret_cast<unsigned*>(dh)[i] = hi;
        reinterpret_cast<unsigned*>(dl)[i] = lo;
    }
}

__global__ __launch_bounds__(256) void tsplit_w(const float* __restrict__ W,
                                                __nv_bfloat16* __restrict__ dh,
                                                __nv_bfloat16* __restrict__ dl,
                                                int K, int NB) {
    __shared__ float tile[32][33];
    const int n0 = blockIdx.x * 32, k0 = blockIdx.y * 32;
    const int tx = threadIdx.x & 31, ty = threadIdx.x >> 5;
    for (int r = ty; r < 32; r += 8)
        tile[r][tx] = W[(size_t)(k0 + r) * NB + n0 + tx];
    __syncthreads();
    for (int u = threadIdx.x; u < 512; u += 256) {
        const int rr = u >> 4, c = (u & 15) * 2;
        unsigned hi, lo; split2(tile[c][rr], tile[c + 1][rr], hi, lo);
        const size_t off = ((size_t)(n0 + rr) * K + k0 + c) >> 1;
        reinterpret_cast<unsigned*>(dh)[off] = hi;
        reinterpret_cast<unsigned*>(dl)[off] = lo;
    }
}

// ---------------- HMMA GEMM: 128m x 64n, 4 warps @ 64x32, 2-stage ----------
#define SAH 0
#define SAL 4608
#define SBH 9216
#define SBL 11520
#define GSTG 13824

__global__ __launch_bounds__(128, 2) void mma_gemm(
    const __nv_bfloat16* __restrict__ Ah, const __nv_bfloat16* __restrict__ Al,
    const __nv_bfloat16* __restrict__ Bh, const __nv_bfloat16* __restrict__ Bl,
    float* __restrict__ Cout, int mode) {
    extern __shared__ unsigned su[];
    const unsigned sbase = (unsigned)__cvta_generic_to_shared(su);
    const int K = 1024;
    const int m0 = blockIdx.y * 128, n0 = blockIdx.x * 64;
    const int tid = threadIdx.x, lane = tid & 31, wp = tid >> 5;
    const int g = lane >> 2, t = lane & 3;
    const int rg = (wp >> 1) * 64, cg = wp & 1;

    const uint4* pAh = reinterpret_cast<const uint4*>(Ah + (size_t)m0 * K);
    const uint4* pAl = reinterpret_cast<const uint4*>(Al + (size_t)m0 * K);
    const uint4* pBh = reinterpret_cast<const uint4*>(Bh + (size_t)n0 * K);
    const uint4* pBl = reinterpret_cast<const uint4*>(Bl + (size_t)n0 * K);

    float c16[16][4] = {};

#define GLOAD(ST, K0)                                                          \
    {                                                                          \
        const int kc = (K0) >> 3;                                              \
        const unsigned base = sbase + (ST) * (GSTG * 4);                       \
        for (int idx = tid; idx < 2048; idx += 128) {                          \
            const int half = idx >> 10, r = (idx & 1023) >> 3, c = idx & 7;    \
            cpa16(base + (half ? SAL : SAH) * 4 + (r * 9 + c) * 16,            \
                  (half ? pAl : pAh) + (size_t)r * 128 + kc + c);              \
        }                                                                      \
        for (int idx = tid; idx < 1024; idx += 128) {                          \
            const int half = idx >> 9, r = (idx & 511) >> 3, c = idx & 7;      \
            cpa16(base + (half ? SBL : SBH) * 4 + (r * 9 + c) * 16,            \
                  (half ? pBl : pBh) + (size_t)r * 128 + kc + c);              \
        }                                                                      \
        cp_commit();                                                           \
    }

    GLOAD(0, 0)
    for (int it = 0; it < 16; it++) {
        if (it + 1 < 16) { GLOAD((it + 1) & 1, (it + 1) * 64) cp_wait1(); }
        else cp_wait0();
        __syncthreads();
        mma_tile64(sbase + (it & 1) * (GSTG * 4), SAH, SAL, SBH, SBL,
                   rg, cg * 32, lane, c16);
        __syncthreads();
    }
#undef GLOAD

    if (mode == 0) {
        const int part = n0 >> 10;
        const int b = m0 >> 11;
        const int mloc = m0 & (N_ - 1);
        const int hh = (n0 & 1023) >> 6;
        const int bh = b * H_ + hh;
        if (part < 2) {
            const float SCp = (part == 0) ? 0.03125f : 1.0f;
            unsigned* uh = reinterpret_cast<unsigned*>(part == 0 ? g_qh : g_kh);
            unsigned* ul = reinterpret_cast<unsigned*>(part == 0 ? g_ql : g_kl);
#pragma unroll
            for (int mt = 0; mt < 4; mt++)
#pragma unroll
                for (int nt = 0; nt < 4; nt++) {
                    const float* cc = c16[mt * 4 + nt];
                    const int R0 = mloc + rg + mt * 16 + g;
                    const int d = cg * 32 + nt * 8 + 2 * t;
                    unsigned hi, lo;
                    split2(cc[0] * SCp, cc[1] * SCp, hi, lo);
                    const size_t o0 = (((size_t)bh * N_ + R0) * D_ + d) >> 1;
                    uh[o0] = hi; ul[o0] = lo;
                    split2(cc[2] * SCp, cc[3] * SCp, hi, lo);
                    const size_t o1 = (((size_t)bh * N_ + R0 + 8) * D_ + d) >> 1;
                    uh[o1] = hi; ul[o1] = lo;
                }
        } else {
#pragma unroll
            for (int mt = 0; mt < 4; mt++)
#pragma unroll
                for (int nt = 0; nt < 4; nt++) {
                    const float* cc = c16[mt * 4 + nt];
                    const int i0v = mloc + rg + mt * 16 + g;
                    const int d = cg * 32 + nt * 8 + 2 * t;
                    const size_t b0 = ((size_t)bh * D_ + d) * N_;
                    const size_t b1 = ((size_t)bh * D_ + d + 1) * N_;
#pragma unroll
                    for (int q = 0; q < 4; q++) {
                        const float v = cc[q];
                        const size_t off = ((q & 1) ? b1 : b0) + i0v + (q >> 1) * 8;
                        const __nv_bfloat16 hb = __float2bfloat16(v);
                        g_vh[off] = hb;
                        g_vl[off] = __float2bfloat16(v - __bfloat162float(hb));
                    }
                }
        }
    } else {
#pragma unroll
        for (int mt = 0; mt < 4; mt++)
#pragma unroll
            for (int nt = 0; nt < 4; nt++) {
                const float* cc = c16[mt * 4 + nt];
                const int R0 = m0 + rg + mt * 16 + g;
                const int n = n0 + cg * 32 + nt * 8 + 2 * t;
                *reinterpret_cast<float2*>(&Cout[(size_t)R0 * DIM_ + n]) =
                    make_float2(cc[0], cc[1]);
                *reinterpret_cast<float2*>(&Cout[(size_t)(R0 + 8) * DIM_ + n]) =
                    make_float2(cc[2], cc[3]);
            }
    }
}

// ---------------- HMMA segment attention: 256 thr, 8 warps @ m16n64 ---------
// smem words: QH/WH 0 (4608), QL/WL 4608 (4608); stages 9216 + s*4608
// (XH +0, XL +2304); dsh 18432 (512 f, in-place inv). 18944 w = 75776 B
// -> 2 blocks/SM (regs <=128).
#define SQH 0
#define SQL 4608
#define ASST 9216
#define ASDS 18432

#define ACCSEG(DS, SG, E)                                                      \
    { if ((SG) == 0) (DS)[0] += (E); else if ((SG) == 1) (DS)[1] += (E);       \
      else if ((SG) == 2) (DS)[2] += (E); else (DS)[3] += (E); }

__global__ __launch_bounds__(256, 2) void attn_mma(const int* __restrict__ mask) {
    extern __shared__ unsigned su[];
    const unsigned sbase = (unsigned)__cvta_generic_to_shared(su);
    float* dshf = reinterpret_cast<float*>(su + ASDS);
    uint4* su4 = reinterpret_cast<uint4*>(su);

    const int b = blockIdx.z, h = blockIdx.x;
    const int i0 = blockIdx.y * 128;
    const int bh = b * H_ + h;
    const int tid = threadIdx.x;
    const int lane = tid & 31, wp = tid >> 5;
    const int g = lane >> 2, t = lane & 3;
    const int r0 = wp * 16 + g, r1 = r0 + 8;
    const int* mrow = mask + (size_t)b * N_ * N_ + (size_t)i0 * N_;
    float* eblk = g_e + (((size_t)bh * 16 + blockIdx.y) << 18);

    // load Q tile (hi/lo)
    {
        const uint4* gqh = reinterpret_cast<const uint4*>(g_qh + ((size_t)bh * N_ + i0) * D_);
        const uint4* gql = reinterpret_cast<const uint4*>(g_ql + ((size_t)bh * N_ + i0) * D_);
        for (int idx = tid; idx < 1024; idx += 256) {
            const int r = idx >> 3, c = idx & 7;
            su4[(SQH >> 2) + r * 9 + c] = gqh[idx];
            su4[(SQL >> 2) + r * 9 + c] = gql[idx];
        }
    }

    const uint4* gkh = reinterpret_cast<const uint4*>(g_kh + (size_t)bh * N_ * D_);
    const uint4* gkl = reinterpret_cast<const uint4*>(g_kl + (size_t)bh * N_ * D_);
    const uint4* gvh = reinterpret_cast<const uint4*>(g_vh + (size_t)bh * D_ * N_);
    const uint4* gvl = reinterpret_cast<const uint4*>(g_vl + (size_t)bh * D_ * N_);

#define LOADK(ST, JT)                                                          \
    {                                                                          \
        const unsigned base = sbase + (ASST + (ST) * 4608) * 4;                \
        const int jr = (JT) * 512;                                             \
        for (int idx = tid; idx < 1024; idx += 256) {                          \
            const int half = idx >> 9, r = (idx & 511) >> 3, c = idx & 7;      \
            cpa16(base + half * 9216 + (r * 9 + c) * 16,                       \
                  (half ? gkl : gkh) + jr + (size_t)r * 8 + c);                \
        }                                                                      \
        cp_commit();                                                           \
    }
#define LOADV(ST, JT)                                                          \
    {                                                                          \
        const unsigned base = sbase + (ASST + (ST) * 4608) * 4;                \
        const int jc = (JT) * 8;                                               \
        for (int idx = tid; idx < 1024; idx += 256) {                          \
            const int half = idx >> 9, r = (idx & 511) >> 3, c = idx & 7;      \
            cpa16(base + half * 9216 + (r * 9 + c) * 16,                       \
                  (half ? gvl : gvh) + (size_t)r * 256 + jc + c);              \
        }                                                                      \
        cp_commit();                                                           \
    }

    // ---------------- PASS 1: denominators + e store ----------------
    float ds0[4] = {0.f, 0.f, 0.f, 0.f}, ds1[4] = {0.f, 0.f, 0.f, 0.f};
    LOADK(0, 0)
    for (int jt = 0; jt < 32; jt++) {
        if (jt + 1 < 32) { LOADK((jt + 1) & 1, jt + 1) cp_wait1(); }
        else cp_wait0();
        __syncthreads();
        const int koff = ASST + (jt & 1) * 4608;
        float c8[8][4] = {};
        mma_tile(sbase, SQH, SQL, koff, koff + 2304, wp * 16, lane, c8);
        __syncthreads();
        float* ew = eblk + ((size_t)jt * 8 + wp) * 1024;
        const int j0 = jt * 64;
#pragma unroll
        for (int nt = 0; nt < 8; nt++) {
            const int jc = j0 + nt * 8 + 2 * t;
            const int2 m0 = *reinterpret_cast<const int2*>(&mrow[(size_t)r0 * N_ + jc]);
            const int2 m1 = *reinterpret_cast<const int2*>(&mrow[(size_t)r1 * N_ + jc]);
            const float e0 = __expf(c8[nt][0]), e1 = __expf(c8[nt][1]);
            const float e2 = __expf(c8[nt][2]), e3 = __expf(c8[nt][3]);
            ACCSEG(ds0, m0.x, e0) ACCSEG(ds0, m0.y, e1)
            ACCSEG(ds1, m1.x, e2) ACCSEG(ds1, m1.y, e3)
            *reinterpret_cast<float2*>(&ew[nt * 128 + g * 8 + 2 * t]) =
                make_float2(e0, e1);
            *reinterpret_cast<float2*>(&ew[nt * 128 + 64 + g * 8 + 2 * t]) =
                make_float2(e2, e3);
        }
    }
#pragma unroll
    for (int s = 0; s < 4; s++) {
        float v0 = ds0[s], v1 = ds1[s];
        v0 += __shfl_xor_sync(0xffffffffu, v0, 1);
        v0 += __shfl_xor_sync(0xffffffffu, v0, 2);
        v1 += __shfl_xor_sync(0xffffffffu, v1, 1);
        v1 += __shfl_xor_sync(0xffffffffu, v1, 2);
        if (t == 0) { dshf[r0 * 4 + s] = v0; dshf[r1 * 4 + s] = v1; }
    }
    __syncthreads();
    for (int idx = tid; idx < 512; idx += 256) {
        const float dv = dshf[idx];
        dshf[idx] = (dv == 0.0f) ? 1.0f : 1.0f / dv;
    }
    __syncthreads();

    // ---------------- PASS 2: w = e*invd -> O += w @ V (W overlaps Q) -------
    float o8[8][4] = {};
    LOADV(0, 0)
    for (int jt = 0; jt < 32; jt++) {
        if (jt + 1 < 32) LOADV((jt + 1) & 1, jt + 1)
        const float* ew = eblk + ((size_t)jt * 8 + wp) * 1024;
        const int j0 = jt * 64;
        const float iv0[4] = {dshf[r0 * 4 + 0], dshf[r0 * 4 + 1],
                              dshf[r0 * 4 + 2], dshf[r0 * 4 + 3]};
        const float iv1[4] = {dshf[r1 * 4 + 0], dshf[r1 * 4 + 1],
                              dshf[r1 * 4 + 2], dshf[r1 * 4 + 3]};
#pragma unroll
        for (int nt = 0; nt < 8; nt++) {
            const int jc = j0 + nt * 8 + 2 * t;
            const int2 m0 = *reinterpret_cast<const int2*>(&mrow[(size_t)r0 * N_ + jc]);
            const int2 m1 = *reinterpret_cast<const int2*>(&mrow[(size_t)r1 * N_ + jc]);
            const float2 eA = *reinterpret_cast<const float2*>(&ew[nt * 128 + g * 8 + 2 * t]);
            const float2 eB = *reinterpret_cast<const float2*>(&ew[nt * 128 + 64 + g * 8 + 2 * t]);
            unsigned hi, lo;
            split2(eA.x * iv0[m0.x], eA.y * iv0[m0.y], hi, lo);
            su[SQH + r0 * 36 + nt * 4 + t] = hi;
            su[SQL + r0 * 36 + nt * 4 + t] = lo;
            split2(eB.x * iv1[m1.x], eB.y * iv1[m1.y], hi, lo);
            su[SQH + r1 * 36 + nt * 4 + t] = hi;
            su[SQL + r1 * 36 + nt * 4 + t] = lo;
        }
        if (jt + 1 < 32) cp_wait1(); else cp_wait0();
        __syncthreads();
        const int voff = ASST + (jt & 1) * 4608;
        mma_tile(sbase, SQH, SQL, voff, voff + 2304, wp * 16, lane, o8);
        __syncthreads();
    }
#undef LOADK
#undef LOADV

    // store O as split bf16
    {
        unsigned* ah = reinterpret_cast<unsigned*>(g_ah);
        unsigned* al = reinterpret_cast<unsigned*>(g_al);
#pragma unroll
        for (int nt = 0; nt < 8; nt++) {
            const int d = h * 64 + nt * 8 + 2 * t;
            unsigned hi, lo;
            split2(o8[nt][0], o8[nt][1], hi, lo);
            const size_t o0 = ((size_t)(b * N_ + i0 + r0) * DIM_ + d) >> 1;
            ah[o0] = hi; al[o0] = lo;
            split2(o8[nt][2], o8[nt][3], hi, lo);
            const size_t o1 = ((size_t)(b * N_ + i0 + r1) * DIM_ + d) >> 1;
            ah[o1] = hi; al[o1] = lo;
        }
    }
}

// ---------------------------------------------------------------------------
extern "C" void kernel_launch(void* const* d_in, const int* in_sizes, int n_in,
                              void* d_out, int out_size) {
    const float* features = (const float*)d_in[0];
    const int*   mask     = (const int*)d_in[1];
    const float* W_qkv    = (const float*)d_in[2];
    const float* W_out    = (const float*)d_in[3];
    float* out = (float*)d_out;

    cudaFuncSetAttribute(attn_mma, cudaFuncAttributeMaxDynamicSharedMemorySize, 75776);
    cudaFuncSetAttribute(mma_gemm, cudaFuncAttributeMaxDynamicSharedMemorySize, 110592);

    __nv_bfloat16 *fh, *fl, *wqh, *wql, *woh, *wol, *ah, *al;
    cudaGetSymbolAddress((void**)&fh, g_fh);   cudaGetSymbolAddress((void**)&fl, g_fl);
    cudaGetSymbolAddress((void**)&wqh, g_wqh); cudaGetSymbolAddress((void**)&wql, g_wql);
    cudaGetSymbolAddress((void**)&woh, g_woh); cudaGetSymbolAddress((void**)&wol, g_wol);
    cudaGetSymbolAddress((void**)&ah, g_ah);   cudaGetSymbolAddress((void**)&al, g_al);

    split_f32<<<(M_ * DIM_ / 2 + 255) / 256, 256>>>(features, fh, fl, M_ * DIM_ / 2);
    tsplit_w<<<dim3(3 * DIM_ / 32, DIM_ / 32), 256>>>(W_qkv, wqh, wql, DIM_, 3 * DIM_);
    tsplit_w<<<dim3(DIM_ / 32, DIM_ / 32), 256>>>(W_out, woh, wol, DIM_, DIM_);

    mma_gemm<<<dim3(3 * DIM_ / 64, M_ / 128), 128, 110592>>>(fh, fl, wqh, wql, nullptr, 0);
    attn_mma<<<dim3(H_, N_ / 128, B_), 256, 75776>>>(mask);
    mma_gemm<<<dim3(DIM_ / 64, M_ / 128), 128, 110592>>>(ah, al, woh, wol, out, 1);
}

// round 12
// speedup vs baseline: 1.3867x; 1.0216x over previous
#include <cuda_runtime.h>
#include <cuda_bf16.h>
#include <cuda_fp16.h>
#include <cstdint>

#define B_   2
#define N_   2048
#define DIM_ 1024
#define H_   16
#define D_   64
#define BH_  (B_ * H_)
#define M_   (B_ * N_)

// ---- device scratch (allocation-free rule) ----
__device__ __nv_bfloat16 g_fh[(size_t)M_ * DIM_];
__device__ __nv_bfloat16 g_fl[(size_t)M_ * DIM_];
__device__ __nv_bfloat16 g_wqh[(size_t)3 * DIM_ * DIM_];
__device__ __nv_bfloat16 g_wql[(size_t)3 * DIM_ * DIM_];
__device__ __nv_bfloat16 g_woh[(size_t)DIM_ * DIM_];
__device__ __nv_bfloat16 g_wol[(size_t)DIM_ * DIM_];
__device__ __nv_bfloat16 g_qh[(size_t)BH_ * N_ * D_];
__device__ __nv_bfloat16 g_ql[(size_t)BH_ * N_ * D_];
__device__ __nv_bfloat16 g_kh[(size_t)BH_ * N_ * D_];
__device__ __nv_bfloat16 g_kl[(size_t)BH_ * N_ * D_];
__device__ __nv_bfloat16 g_vh[(size_t)BH_ * D_ * N_];
__device__ __nv_bfloat16 g_vl[(size_t)BH_ * D_ * N_];
__device__ __nv_bfloat16 g_ah[(size_t)M_ * DIM_];
__device__ __nv_bfloat16 g_al[(size_t)M_ * DIM_];
__device__ unsigned g_e[(size_t)BH_ * N_ * N_ / 2];   // exp(scores) fp16x2, warp-packed

__device__ __forceinline__ unsigned b2u(__nv_bfloat162 v) {
    return *reinterpret_cast<unsigned*>(&v);
}
__device__ __forceinline__ void split2(float x0, float x1, unsigned& hi, unsigned& lo) {
    __nv_bfloat162 h2 = __floats2bfloat162_rn(x0, x1);
    __nv_bfloat162 l2 = __floats2bfloat162_rn(x0 - __bfloat162float(h2.x),
                                              x1 - __bfloat162float(h2.y));
    hi = b2u(h2); lo = b2u(l2);
}

__device__ __forceinline__ void mma16816(float* c, unsigned a0, unsigned a1,
                                         unsigned a2, unsigned a3,
                                         unsigned b0, unsigned b1) {
    asm("mma.sync.aligned.m16n8k16.row.col.f32.bf16.bf16.f32 "
        "{%0,%1,%2,%3},{%4,%5,%6,%7},{%8,%9},{%0,%1,%2,%3};\n"
        : "+f"(c[0]), "+f"(c[1]), "+f"(c[2]), "+f"(c[3])
        : "r"(a0), "r"(a1), "r"(a2), "r"(a3), "r"(b0), "r"(b1));
}

__device__ __forceinline__ void ldsm4(unsigned addr, unsigned& r0, unsigned& r1,
                                      unsigned& r2, unsigned& r3) {
    asm volatile("ldmatrix.sync.aligned.m8n8.x4.shared.b16 {%0,%1,%2,%3}, [%4];\n"
                 : "=r"(r0), "=r"(r1), "=r"(r2), "=r"(r3) : "r"(addr));
}

__device__ __forceinline__ void cpa16(unsigned dst, const void* src) {
    asm volatile("cp.async.cg.shared.global [%0], [%1], 16;\n" :: "r"(dst), "l"(src));
}
__device__ __forceinline__ void cp_commit() { asm volatile("cp.async.commit_group;\n"); }
__device__ __forceinline__ void cp_wait1() { asm volatile("cp.async.wait_group 1;\n"); }
__device__ __forceinline__ void cp_wait0() { asm volatile("cp.async.wait_group 0;\n"); }

__device__ __forceinline__ unsigned packf16(float lo, float hi) {
    unsigned u;
    asm("cvt.rn.f16x2.f32 %0, %1, %2;" : "=r"(u) : "f"(hi), "f"(lo));
    return u;
}

// ---------------------------------------------------------------------------
// m64 x n32 x k64 warp-tile block-MMA (GEMM), hi/lo split, stride 36 words.
// ---------------------------------------------------------------------------
__device__ __forceinline__ void mma_tile64(unsigned sb, int AH, int AL,
                                           int BHo, int BLo, int arow, int bcol,
                                           int lane, float c[16][4]) {
    const int m = lane >> 3, r = lane & 7;
    const unsigned paw = (unsigned)((arow + (m & 1) * 8 + r) * 36 + (m >> 1) * 4) * 4;
    const unsigned pbw = (unsigned)((bcol + (m >> 1) * 8 + r) * 36 + (m & 1) * 4) * 4;
#pragma unroll
    for (int ks = 0; ks < 4; ks++) {
        unsigned ah[4][4], al_[4][4];
#pragma unroll
        for (int mt = 0; mt < 4; mt++) {
            ldsm4(sb + AH * 4 + paw + mt * (16 * 36 * 4) + ks * 32,
                  ah[mt][0], ah[mt][1], ah[mt][2], ah[mt][3]);
            ldsm4(sb + AL * 4 + paw + mt * (16 * 36 * 4) + ks * 32,
                  al_[mt][0], al_[mt][1], al_[mt][2], al_[mt][3]);
        }
#pragma unroll
        for (int np = 0; np < 2; np++) {
            unsigned bh[4], bl[4];
            ldsm4(sb + BHo * 4 + pbw + np * (16 * 36 * 4) + ks * 32,
                  bh[0], bh[1], bh[2], bh[3]);
            ldsm4(sb + BLo * 4 + pbw + np * (16 * 36 * 4) + ks * 32,
                  bl[0], bl[1], bl[2], bl[3]);
#pragma unroll
            for (int mt = 0; mt < 4; mt++) {
                float* c0 = c[mt * 4 + np * 2 + 0];
                float* c1 = c[mt * 4 + np * 2 + 1];
                mma16816(c0, ah[mt][0], ah[mt][1], ah[mt][2], ah[mt][3], bh[0], bh[1]);
                mma16816(c0, ah[mt][0], ah[mt][1], ah[mt][2], ah[mt][3], bl[0], bl[1]);
                mma16816(c0, al_[mt][0], al_[mt][1], al_[mt][2], al_[mt][3], bh[0], bh[1]);
                mma16816(c1, ah[mt][0], ah[mt][1], ah[mt][2], ah[mt][3], bh[2], bh[3]);
                mma16816(c1, ah[mt][0], ah[mt][1], ah[mt][2], ah[mt][3], bl[2], bl[3]);
                mma16816(c1, al_[mt][0], al_[mt][1], al_[mt][2], al_[mt][3], bh[2], bh[3]);
            }
        }
    }
}

// m16 x n64 x k64 warp-tile (attention), hi/lo split, stride 36 words.
__device__ __forceinline__ void mma_tile(unsigned sb, int AH, int AL,
                                         int BHo, int BLo, int arow, int lane,
                                         float c[8][4]) {
    const int m = lane >> 3, r = lane & 7;
    const unsigned pa = ((unsigned)(arow + (m & 1) * 8 + r) * 36 + (m >> 1) * 4) * 4;
    const unsigned pb = (((unsigned)((m >> 1) * 8 + r)) * 36 + (m & 1) * 4) * 4;
#pragma unroll
    for (int ks = 0; ks < 4; ks++) {
        unsigned ah0, ah1, ah2, ah3, al0, al1, al2, al3;
        ldsm4(sb + AH * 4 + pa + ks * 32, ah0, ah1, ah2, ah3);
        ldsm4(sb + AL * 4 + pa + ks * 32, al0, al1, al2, al3);
#pragma unroll
        for (int ntp = 0; ntp < 4; ntp++) {
            unsigned bh0, bh1, bh2, bh3, bl0, bl1, bl2, bl3;
            const unsigned bofs = pb + ntp * (16 * 36 * 4) + ks * 32;
            ldsm4(sb + BHo * 4 + bofs, bh0, bh1, bh2, bh3);
            ldsm4(sb + BLo * 4 + bofs, bl0, bl1, bl2, bl3);
            mma16816(c[2 * ntp + 0], ah0, ah1, ah2, ah3, bh0, bh1);
            mma16816(c[2 * ntp + 0], ah0, ah1, ah2, ah3, bl0, bl1);
            mma16816(c[2 * ntp + 0], al0, al1, al2, al3, bh0, bh1);
            mma16816(c[2 * ntp + 1], ah0, ah1, ah2, ah3, bh2, bh3);
            mma16816(c[2 * ntp + 1], ah0, ah1, ah2, ah3, bl2, bl3);
            mma16816(c[2 * ntp + 1], al0, al1, al2, al3, bh2, bh3);
        }
    }
}

// ---------------- preprocess: splits ----------------
__global__ __launch_bounds__(256) void split_f32(const float* __restrict__ src,
                                                 __nv_bfloat16* __restrict__ dh,
                                                 __nv_bfloat16* __restrict__ dl,
                                                 int n2) {
    int i = blockIdx.x * 256 + threadIdx.x;
    if (i < n2) {
        float2 v = reinterpret_cast<const float2*>(src)[i];
        unsigned hi, lo; split2(v.x, v.y, hi, lo);
        reinterpret_cast<unsigned*>(dh)[i] = hi;
        reinterpret_cast<unsigned*>(dl)[i] = lo;
    }
}

__global__ __launch_bounds__(256) void tsplit_w(const float* __restrict__ W,
                                                __nv_bfloat16* __restrict__ dh,
                                                __nv_bfloat16* __restrict__ dl,
                                                int K, int NB) {
    __shared__ float tile[32][33];
    const int n0 = blockIdx.x * 32, k0 = blockIdx.y * 32;
    const int tx = threadIdx.x & 31, ty = threadIdx.x >> 5;
    for (int r = ty; r < 32; r += 8)
        tile[r][tx] = W[(size_t)(k0 + r) * NB + n0 + tx];
    __syncthreads();
    for (int u = threadIdx.x; u < 512; u += 256) {
        const int rr = u >> 4, c = (u & 15) * 2;
        unsigned hi, lo; split2(tile[c][rr], tile[c + 1][rr], hi, lo);
        const size_t off = ((size_t)(n0 + rr) * K + k0 + c) >> 1;
        reinterpret_cast<unsigned*>(dh)[off] = hi;
        reinterpret_cast<unsigned*>(dl)[off] = lo;
    }
}

// ---------------- HMMA GEMM: 128m x 64n, 4 warps @ 64x32, 2-stage ----------
#define SAH 0
#define SAL 4608
#define SBH 9216
#define SBL 11520
#define GSTG 13824

__global__ __launch_bounds__(128, 2) void mma_gemm(
    const __nv_bfloat16* __restrict__ Ah, const __nv_bfloat16* __restrict__ Al,
    const __nv_bfloat16* __restrict__ Bh, const __nv_bfloat16* __restrict__ Bl,
    float* __restrict__ Cout, int mode) {
    extern __shared__ unsigned su[];
    const unsigned sbase = (unsigned)__cvta_generic_to_shared(su);
    const int K = 1024;
    const int m0 = blockIdx.y * 128, n0 = blockIdx.x * 64;
    const int tid = threadIdx.x, lane = tid & 31, wp = tid >> 5;
    const int g = lane >> 2, t = lane & 3;
    const int rg = (wp >> 1) * 64, cg = wp & 1;

    const uint4* pAh = reinterpret_cast<const uint4*>(Ah + (size_t)m0 * K);
    const uint4* pAl = reinterpret_cast<const uint4*>(Al + (size_t)m0 * K);
    const uint4* pBh = reinterpret_cast<const uint4*>(Bh + (size_t)n0 * K);
    const uint4* pBl = reinterpret_cast<const uint4*>(Bl + (size_t)n0 * K);

    float c16[16][4] = {};

#define GLOAD(ST, K0)                                                          \
    {                                                                          \
        const int kc = (K0) >> 3;                                              \
        const unsigned base = sbase + (ST) * (GSTG * 4);                       \
        for (int idx = tid; idx < 2048; idx += 128) {                          \
            const int half = idx >> 10, r = (idx & 1023) >> 3, c = idx & 7;    \
            cpa16(base + (half ? SAL : SAH) * 4 + (r * 9 + c) * 16,            \
                  (half ? pAl : pAh) + (size_t)r * 128 + kc + c);              \
        }                                                                      \
        for (int idx = tid; idx < 1024; idx += 128) {                          \
            const int half = idx >> 9, r = (idx & 511) >> 3, c = idx & 7;      \
            cpa16(base + (half ? SBL : SBH) * 4 + (r * 9 + c) * 16,            \
                  (half ? pBl : pBh) + (size_t)r * 128 + kc + c);              \
        }                                                                      \
        cp_commit();                                                           \
    }

    GLOAD(0, 0)
    for (int it = 0; it < 16; it++) {
        if (it + 1 < 16) { GLOAD((it + 1) & 1, (it + 1) * 64) cp_wait1(); }
        else cp_wait0();
        __syncthreads();
        mma_tile64(sbase + (it & 1) * (GSTG * 4), SAH, SAL, SBH, SBL,
                   rg, cg * 32, lane, c16);
        __syncthreads();
    }
#undef GLOAD

    if (mode == 0) {
        const int part = n0 >> 10;
        const int b = m0 >> 11;
        const int mloc = m0 & (N_ - 1);
        const int hh = (n0 & 1023) >> 6;
        const int bh = b * H_ + hh;
        if (part < 2) {
            const float SCp = (part == 0) ? 0.03125f : 1.0f;
            unsigned* uh = reinterpret_cast<unsigned*>(part == 0 ? g_qh : g_kh);
            unsigned* ul = reinterpret_cast<unsigned*>(part == 0 ? g_ql : g_kl);
#pragma unroll
            for (int mt = 0; mt < 4; mt++)
#pragma unroll
                for (int nt = 0; nt < 4; nt++) {
                    const float* cc = c16[mt * 4 + nt];
                    const int R0 = mloc + rg + mt * 16 + g;
                    const int d = cg * 32 + nt * 8 + 2 * t;
                    unsigned hi, lo;
                    split2(cc[0] * SCp, cc[1] * SCp, hi, lo);
                    const size_t o0 = (((size_t)bh * N_ + R0) * D_ + d) >> 1;
                    uh[o0] = hi; ul[o0] = lo;
                    split2(cc[2] * SCp, cc[3] * SCp, hi, lo);
                    const size_t o1 = (((size_t)bh * N_ + R0 + 8) * D_ + d) >> 1;
                    uh[o1] = hi; ul[o1] = lo;
                }
        } else {
#pragma unroll
            for (int mt = 0; mt < 4; mt++)
#pragma unroll
                for (int nt = 0; nt < 4; nt++) {
                    const float* cc = c16[mt * 4 + nt];
                    const int i0v = mloc + rg + mt * 16 + g;
                    const int d = cg * 32 + nt * 8 + 2 * t;
                    const size_t b0 = ((size_t)bh * D_ + d) * N_;
                    const size_t b1 = ((size_t)bh * D_ + d + 1) * N_;
#pragma unroll
                    for (int q = 0; q < 4; q++) {
                        const float v = cc[q];
                        const size_t off = ((q & 1) ? b1 : b0) + i0v + (q >> 1) * 8;
                        const __nv_bfloat16 hb = __float2bfloat16(v);
                        g_vh[off] = hb;
                        g_vl[off] = __float2bfloat16(v - __bfloat162float(hb));
                    }
                }
        }
    } else {
#pragma unroll
        for (int mt = 0; mt < 4; mt++)
#pragma unroll
            for (int nt = 0; nt < 4; nt++) {
                const float* cc = c16[mt * 4 + nt];
                const int R0 = m0 + rg + mt * 16 + g;
                const int n = n0 + cg * 32 + nt * 8 + 2 * t;
                *reinterpret_cast<float2*>(&Cout[(size_t)R0 * DIM_ + n]) =
                    make_float2(cc[0], cc[1]);
                *reinterpret_cast<float2*>(&Cout[(size_t)(R0 + 8) * DIM_ + n]) =
                    make_float2(cc[2], cc[3]);
            }
    }
}

// ---------------- HMMA segment attention: 256 thr, 8 warps @ m16n64 ---------
// smem words: QH/WH 0 (4608), QL/WL 4608 (4608); stages 9216 + s*4608
// (XH +0, XL +2304); dsh 18432 (512 f, in-place inv). 18944 w = 75776 B
#define SQH 0
#define SQL 4608
#define ASST 9216
#define ASDS 18432

#define ACCSEG(DS, SG, E)                                                      \
    { if ((SG) == 0) (DS)[0] += (E); else if ((SG) == 1) (DS)[1] += (E);       \
      else if ((SG) == 2) (DS)[2] += (E); else (DS)[3] += (E); }

__global__ __launch_bounds__(256, 2) void attn_mma(const int* __restrict__ mask) {
    extern __shared__ unsigned su[];
    const unsigned sbase = (unsigned)__cvta_generic_to_shared(su);
    float* dshf = reinterpret_cast<float*>(su + ASDS);
    uint4* su4 = reinterpret_cast<uint4*>(su);

    const int b = blockIdx.z, h = blockIdx.x;
    const int i0 = blockIdx.y * 128;
    const int bh = b * H_ + h;
    const int tid = threadIdx.x;
    const int lane = tid & 31, wp = tid >> 5;
    const int g = lane >> 2, t = lane & 3;
    const int r0 = wp * 16 + g, r1 = r0 + 8;
    const int* mrow = mask + (size_t)b * N_ * N_ + (size_t)i0 * N_;
    // e block: per (bh, i-block): 32 jt x 8 warps x 512 u32 = 1<<17
    unsigned* eblk = g_e + (((size_t)bh * 16 + blockIdx.y) << 17);

    // load Q tile (hi/lo)
    {
        const uint4* gqh = reinterpret_cast<const uint4*>(g_qh + ((size_t)bh * N_ + i0) * D_);
        const uint4* gql = reinterpret_cast<const uint4*>(g_ql + ((size_t)bh * N_ + i0) * D_);
        for (int idx = tid; idx < 1024; idx += 256) {
            const int r = idx >> 3, c = idx & 7;
            su4[(SQH >> 2) + r * 9 + c] = gqh[idx];
            su4[(SQL >> 2) + r * 9 + c] = gql[idx];
        }
    }

    const uint4* gkh = reinterpret_cast<const uint4*>(g_kh + (size_t)bh * N_ * D_);
    const uint4* gkl = reinterpret_cast<const uint4*>(g_kl + (size_t)bh * N_ * D_);
    const uint4* gvh = reinterpret_cast<const uint4*>(g_vh + (size_t)bh * D_ * N_);
    const uint4* gvl = reinterpret_cast<const uint4*>(g_vl + (size_t)bh * D_ * N_);

#define LOADK(ST, JT)                                                          \
    {                                                                          \
        const unsigned base = sbase + (ASST + (ST) * 4608) * 4;                \
        const int jr = (JT) * 512;                                             \
        for (int idx = tid; idx < 1024; idx += 256) {                          \
            const int half = idx >> 9, r = (idx & 511) >> 3, c = idx & 7;      \
            cpa16(base + half * 9216 + (r * 9 + c) * 16,                       \
                  (half ? gkl : gkh) + jr + (size_t)r * 8 + c);                \
        }                                                                      \
        cp_commit();                                                           \
    }
#define LOADV(ST, JT)                                                          \
    {                                                                          \
        const unsigned base = sbase + (ASST + (ST) * 4608) * 4;                \
        const int jc = (JT) * 8;                                               \
        for (int idx = tid; idx < 1024; idx += 256) {                          \
            const int half = idx >> 9, r = (idx & 511) >> 3, c = idx & 7;      \
            cpa16(base + half * 9216 + (r * 9 + c) * 16,                       \
                  (half ? gvl : gvh) + (size_t)r * 256 + jc + c);              \
        }                                                                      \
        cp_commit();                                                           \
    }

    // ---------------- PASS 1: denominators + e store (fp16x2) ----------------
    float ds0[4] = {0.f, 0.f, 0.f, 0.f}, ds1[4] = {0.f, 0.f, 0.f, 0.f};
    LOADK(0, 0)
    for (int jt = 0; jt < 32; jt++) {
        if (jt + 1 < 32) { LOADK((jt + 1) & 1, jt + 1) cp_wait1(); }
        else cp_wait0();
        __syncthreads();
        const int koff = ASST + (jt & 1) * 4608;
        float c8[8][4] = {};
        mma_tile(sbase, SQH, SQL, koff, koff + 2304, wp * 16, lane, c8);
        __syncthreads();
        unsigned* ew = eblk + ((size_t)jt * 8 + wp) * 512;
        const int j0 = jt * 64;
#pragma unroll
        for (int nt = 0; nt < 8; nt++) {
            const int jc = j0 + nt * 8 + 2 * t;
            const int2 m0 = *reinterpret_cast<const int2*>(&mrow[(size_t)r0 * N_ + jc]);
            const int2 m1 = *reinterpret_cast<const int2*>(&mrow[(size_t)r1 * N_ + jc]);
            const float e0 = __expf(c8[nt][0]), e1 = __expf(c8[nt][1]);
            const float e2 = __expf(c8[nt][2]), e3 = __expf(c8[nt][3]);
            ACCSEG(ds0, m0.x, e0) ACCSEG(ds0, m0.y, e1)
            ACCSEG(ds1, m1.x, e2) ACCSEG(ds1, m1.y, e3)
            ew[nt * 64 + lane] = packf16(e0, e1);
            ew[nt * 64 + 32 + lane] = packf16(e2, e3);
        }
    }
#pragma unroll
    for (int s = 0; s < 4; s++) {
        float v0 = ds0[s], v1 = ds1[s];
        v0 += __shfl_xor_sync(0xffffffffu, v0, 1);
        v0 += __shfl_xor_sync(0xffffffffu, v0, 2);
        v1 += __shfl_xor_sync(0xffffffffu, v1, 1);
        v1 += __shfl_xor_sync(0xffffffffu, v1, 2);
        if (t == 0) { dshf[r0 * 4 + s] = v0; dshf[r1 * 4 + s] = v1; }
    }
    __syncthreads();
    for (int idx = tid; idx < 512; idx += 256) {
        const float dv = dshf[idx];
        dshf[idx] = (dv == 0.0f) ? 1.0f : 1.0f / dv;
    }
    __syncthreads();

    // ---------------- PASS 2: w = e*invd -> O += w @ V (W overlaps Q) -------
    float o8[8][4] = {};
    LOADV(0, 0)
    for (int jt = 0; jt < 32; jt++) {
        if (jt + 1 < 32) LOADV((jt + 1) & 1, jt + 1)
        const unsigned* ew = eblk + ((size_t)jt * 8 + wp) * 512;
        const int j0 = jt * 64;
#pragma unroll
        for (int nt = 0; nt < 8; nt++) {
            const int jc = j0 + nt * 8 + 2 * t;
            const int2 m0 = *reinterpret_cast<const int2*>(&mrow[(size_t)r0 * N_ + jc]);
            const int2 m1 = *reinterpret_cast<const int2*>(&mrow[(size_t)r1 * N_ + jc]);
            const unsigned uA = ew[nt * 64 + lane];
            const unsigned uB = ew[nt * 64 + 32 + lane];
            const float2 eA = __half22float2(*reinterpret_cast<const __half2*>(&uA));
            const float2 eB = __half22float2(*reinterpret_cast<const __half2*>(&uB));
            unsigned hi, lo;
            split2(eA.x * dshf[r0 * 4 + m0.x], eA.y * dshf[r0 * 4 + m0.y], hi, lo);
            su[SQH + r0 * 36 + nt * 4 + t] = hi;
            su[SQL + r0 * 36 + nt * 4 + t] = lo;
            split2(eB.x * dshf[r1 * 4 + m1.x], eB.y * dshf[r1 * 4 + m1.y], hi, lo);
            su[SQH + r1 * 36 + nt * 4 + t] = hi;
            su[SQL + r1 * 36 + nt * 4 + t] = lo;
        }
        if (jt + 1 < 32) cp_wait1(); else cp_wait0();
        __syncthreads();
        const int voff = ASST + (jt & 1) * 4608;
        mma_tile(sbase, SQH, SQL, voff, voff + 2304, wp * 16, lane, o8);
        __syncthreads();
    }
#undef LOADK
#undef LOADV

    // store O as split bf16
    {
        unsigned* ah = reinterpret_cast<unsigned*>(g_ah);
        unsigned* al = reinterpret_cast<unsigned*>(g_al);
#pragma unroll
        for (int nt = 0; nt < 8; nt++) {
            const int d = h * 64 + nt * 8 + 2 * t;
            unsigned hi, lo;
            split2(o8[nt][0], o8[nt][1], hi, lo);
            const size_t o0 = ((size_t)(b * N_ + i0 + r0) * DIM_ + d) >> 1;
            ah[o0] = hi; al[o0] = lo;
            split2(o8[nt][2], o8[nt][3], hi, lo);
            const size_t o1 = ((size_t)(b * N_ + i0 + r1) * DIM_ + d) >> 1;
            ah[o1] = hi; al[o1] = lo;
        }
    }
}

// ---------------------------------------------------------------------------
extern "C" void kernel_launch(void* const* d_in, const int* in_sizes, int n_in,
                              void* d_out, int out_size) {
    const float* features = (const float*)d_in[0];
    const int*   mask     = (const int*)d_in[1];
    const float* W_qkv    = (const float*)d_in[2];
    const float* W_out    = (const float*)d_in[3];
    float* out = (float*)d_out;

    cudaFuncSetAttribute(attn_mma, cudaFuncAttributeMaxDynamicSharedMemorySize, 75776);
    cudaFuncSetAttribute(mma_gemm, cudaFuncAttributeMaxDynamicSharedMemorySize, 110592);

    __nv_bfloat16 *fh, *fl, *wqh, *wql, *woh, *wol, *ah, *al;
    cudaGetSymbolAddress((void**)&fh, g_fh);   cudaGetSymbolAddress((void**)&fl, g_fl);
    cudaGetSymbolAddress((void**)&wqh, g_wqh); cudaGetSymbolAddress((void**)&wql, g_wql);
    cudaGetSymbolAddress((void**)&woh, g_woh); cudaGetSymbolAddress((void**)&wol, g_wol);
    cudaGetSymbolAddress((void**)&ah, g_ah);   cudaGetSymbolAddress((void**)&al, g_al);

    split_f32<<<(M_ * DIM_ / 2 + 255) / 256, 256>>>(features, fh, fl, M_ * DIM_ / 2);
    tsplit_w<<<dim3(3 * DIM_ / 32, DIM_ / 32), 256>>>(W_qkv, wqh, wql, DIM_, 3 * DIM_);
    tsplit_w<<<dim3(DIM_ / 32, DIM_ / 32), 256>>>(W_out, woh, wol, DIM_, DIM_);

    mma_gemm<<<dim3(3 * DIM_ / 64, M_ / 128), 128, 110592>>>(fh, fl, wqh, wql, nullptr, 0);
    attn_mma<<<dim3(H_, N_ / 128, B_), 256, 75776>>>(mask);
    mma_gemm<<<dim3(DIM_ / 64, M_ / 128), 128, 110592>>>(ah, al, woh, wol, out, 1);
}

// round 13
// speedup vs baseline: 1.4285x; 1.0301x over previous
#include <cuda_runtime.h>
#include <cuda_bf16.h>
#include <cuda_fp16.h>
#include <cstdint>

#define B_   2
#define N_   2048
#define DIM_ 1024
#define H_   16
#define D_   64
#define BH_  (B_ * H_)
#define M_   (B_ * N_)

// ---- device scratch (allocation-free rule) ----
__device__ __nv_bfloat16 g_fh[(size_t)M_ * DIM_];
__device__ __nv_bfloat16 g_fl[(size_t)M_ * DIM_];
__device__ __nv_bfloat16 g_wqh[(size_t)3 * DIM_ * DIM_];
__device__ __nv_bfloat16 g_wql[(size_t)3 * DIM_ * DIM_];
__device__ __nv_bfloat16 g_woh[(size_t)DIM_ * DIM_];
__device__ __nv_bfloat16 g_wol[(size_t)DIM_ * DIM_];
__device__ __nv_bfloat16 g_qh[(size_t)BH_ * N_ * D_];
__device__ __nv_bfloat16 g_ql[(size_t)BH_ * N_ * D_];
__device__ __nv_bfloat16 g_kh[(size_t)BH_ * N_ * D_];
__device__ __nv_bfloat16 g_kl[(size_t)BH_ * N_ * D_];
__device__ __half g_vh[(size_t)BH_ * D_ * N_];        // V fp16 split
__device__ __half g_vl[(size_t)BH_ * D_ * N_];
__device__ __nv_bfloat16 g_ah[(size_t)M_ * DIM_];
__device__ __nv_bfloat16 g_al[(size_t)M_ * DIM_];
__device__ unsigned g_e[(size_t)BH_ * N_ * N_ / 2];   // exp(scores) fp16x2, warp-packed

__device__ __forceinline__ unsigned b2u(__nv_bfloat162 v) {
    return *reinterpret_cast<unsigned*>(&v);
}
__device__ __forceinline__ void split2(float x0, float x1, unsigned& hi, unsigned& lo) {
    __nv_bfloat162 h2 = __floats2bfloat162_rn(x0, x1);
    __nv_bfloat162 l2 = __floats2bfloat162_rn(x0 - __bfloat162float(h2.x),
                                              x1 - __bfloat162float(h2.y));
    hi = b2u(h2); lo = b2u(l2);
}

__device__ __forceinline__ void mma16816(float* c, unsigned a0, unsigned a1,
                                         unsigned a2, unsigned a3,
                                         unsigned b0, unsigned b1) {
    asm("mma.sync.aligned.m16n8k16.row.col.f32.bf16.bf16.f32 "
        "{%0,%1,%2,%3},{%4,%5,%6,%7},{%8,%9},{%0,%1,%2,%3};\n"
        : "+f"(c[0]), "+f"(c[1]), "+f"(c[2]), "+f"(c[3])
        : "r"(a0), "r"(a1), "r"(a2), "r"(a3), "r"(b0), "r"(b1));
}
__device__ __forceinline__ void mma16816h(float* c, unsigned a0, unsigned a1,
                                          unsigned a2, unsigned a3,
                                          unsigned b0, unsigned b1) {
    asm("mma.sync.aligned.m16n8k16.row.col.f32.f16.f16.f32 "
        "{%0,%1,%2,%3},{%4,%5,%6,%7},{%8,%9},{%0,%1,%2,%3};\n"
        : "+f"(c[0]), "+f"(c[1]), "+f"(c[2]), "+f"(c[3])
        : "r"(a0), "r"(a1), "r"(a2), "r"(a3), "r"(b0), "r"(b1));
}

__device__ __forceinline__ void ldsm4(unsigned addr, unsigned& r0, unsigned& r1,
                                      unsigned& r2, unsigned& r3) {
    asm volatile("ldmatrix.sync.aligned.m8n8.x4.shared.b16 {%0,%1,%2,%3}, [%4];\n"
                 : "=r"(r0), "=r"(r1), "=r"(r2), "=r"(r3) : "r"(addr));
}

__device__ __forceinline__ void cpa16(unsigned dst, const void* src) {
    asm volatile("cp.async.cg.shared.global [%0], [%1], 16;\n" :: "r"(dst), "l"(src));
}
__device__ __forceinline__ void cp_commit() { asm volatile("cp.async.commit_group;\n"); }
__device__ __forceinline__ void cp_wait1() { asm volatile("cp.async.wait_group 1;\n"); }
__device__ __forceinline__ void cp_wait0() { asm volatile("cp.async.wait_group 0;\n"); }

__device__ __forceinline__ unsigned packf16(float lo, float hi) {
    unsigned u;
    asm("cvt.rn.f16x2.f32 %0, %1, %2;" : "=r"(u) : "f"(hi), "f"(lo));
    return u;
}

// ---------------------------------------------------------------------------
// m64 x n32 x k64 warp-tile block-MMA (GEMM), hi/lo split, stride 36 words.
// ---------------------------------------------------------------------------
__device__ __forceinline__ void mma_tile64(unsigned sb, int AH, int AL,
                                           int BHo, int BLo, int arow, int bcol,
                                           int lane, float c[16][4]) {
    const int m = lane >> 3, r = lane & 7;
    const unsigned paw = (unsigned)((arow + (m & 1) * 8 + r) * 36 + (m >> 1) * 4) * 4;
    const unsigned pbw = (unsigned)((bcol + (m >> 1) * 8 + r) * 36 + (m & 1) * 4) * 4;
#pragma unroll
    for (int ks = 0; ks < 4; ks++) {
        unsigned ah[4][4], al_[4][4];
#pragma unroll
        for (int mt = 0; mt < 4; mt++) {
            ldsm4(sb + AH * 4 + paw + mt * (16 * 36 * 4) + ks * 32,
                  ah[mt][0], ah[mt][1], ah[mt][2], ah[mt][3]);
            ldsm4(sb + AL * 4 + paw + mt * (16 * 36 * 4) + ks * 32,
                  al_[mt][0], al_[mt][1], al_[mt][2], al_[mt][3]);
        }
#pragma unroll
        for (int np = 0; np < 2; np++) {
            unsigned bh[4], bl[4];
            ldsm4(sb + BHo * 4 + pbw + np * (16 * 36 * 4) + ks * 32,
                  bh[0], bh[1], bh[2], bh[3]);
            ldsm4(sb + BLo * 4 + pbw + np * (16 * 36 * 4) + ks * 32,
                  bl[0], bl[1], bl[2], bl[3]);
#pragma unroll
            for (int mt = 0; mt < 4; mt++) {
                float* c0 = c[mt * 4 + np * 2 + 0];
                float* c1 = c[mt * 4 + np * 2 + 1];
                mma16816(c0, ah[mt][0], ah[mt][1], ah[mt][2], ah[mt][3], bh[0], bh[1]);
                mma16816(c0, ah[mt][0], ah[mt][1], ah[mt][2], ah[mt][3], bl[0], bl[1]);
                mma16816(c0, al_[mt][0], al_[mt][1], al_[mt][2], al_[mt][3], bh[0], bh[1]);
                mma16816(c1, ah[mt][0], ah[mt][1], ah[mt][2], ah[mt][3], bh[2], bh[3]);
                mma16816(c1, ah[mt][0], ah[mt][1], ah[mt][2], ah[mt][3], bl[2], bl[3]);
                mma16816(c1, al_[mt][0], al_[mt][1], al_[mt][2], al_[mt][3], bh[2], bh[3]);
            }
        }
    }
}

// m16 x n64 x k64 warp-tile (attention QK), bf16 hi/lo split, stride 36 words.
__device__ __forceinline__ void mma_tile(unsigned sb, int AH, int AL,
                                         int BHo, int BLo, int arow, int lane,
                                         float c[8][4]) {
    const int m = lane >> 3, r = lane & 7;
    const unsigned pa = ((unsigned)(arow + (m & 1) * 8 + r) * 36 + (m >> 1) * 4) * 4;
    const unsigned pb = (((unsigned)((m >> 1) * 8 + r)) * 36 + (m & 1) * 4) * 4;
#pragma unroll
    for (int ks = 0; ks < 4; ks++) {
        unsigned ah0, ah1, ah2, ah3, al0, al1, al2, al3;
        ldsm4(sb + AH * 4 + pa + ks * 32, ah0, ah1, ah2, ah3);
        ldsm4(sb + AL * 4 + pa + ks * 32, al0, al1, al2, al3);
#pragma unroll
        for (int ntp = 0; ntp < 4; ntp++) {
            unsigned bh0, bh1, bh2, bh3, bl0, bl1, bl2, bl3;
            const unsigned bofs = pb + ntp * (16 * 36 * 4) + ks * 32;
            ldsm4(sb + BHo * 4 + bofs, bh0, bh1, bh2, bh3);
            ldsm4(sb + BLo * 4 + bofs, bl0, bl1, bl2, bl3);
            mma16816(c[2 * ntp + 0], ah0, ah1, ah2, ah3, bh0, bh1);
            mma16816(c[2 * ntp + 0], ah0, ah1, ah2, ah3, bl0, bl1);
            mma16816(c[2 * ntp + 0], al0, al1, al2, al3, bh0, bh1);
            mma16816(c[2 * ntp + 1], ah0, ah1, ah2, ah3, bh2, bh3);
            mma16816(c[2 * ntp + 1], ah0, ah1, ah2, ah3, bl2, bl3);
            mma16816(c[2 * ntp + 1], al0, al1, al2, al3, bh2, bh3);
        }
    }
}

// m16 x n64 x k64 warp-tile (attention WV): A single fp16, B fp16 split.
__device__ __forceinline__ void mma_tile_w(unsigned sb, int AW,
                                           int BHo, int BLo, int arow, int lane,
                                           float c[8][4]) {
    const int m = lane >> 3, r = lane & 7;
    const unsigned pa = ((unsigned)(arow + (m & 1) * 8 + r) * 36 + (m >> 1) * 4) * 4;
    const unsigned pb = (((unsigned)((m >> 1) * 8 + r)) * 36 + (m & 1) * 4) * 4;
#pragma unroll
    for (int ks = 0; ks < 4; ks++) {
        unsigned a0, a1, a2, a3;
        ldsm4(sb + AW * 4 + pa + ks * 32, a0, a1, a2, a3);
#pragma unroll
        for (int ntp = 0; ntp < 4; ntp++) {
            unsigned bh0, bh1, bh2, bh3, bl0, bl1, bl2, bl3;
            const unsigned bofs = pb + ntp * (16 * 36 * 4) + ks * 32;
            ldsm4(sb + BHo * 4 + bofs, bh0, bh1, bh2, bh3);
            ldsm4(sb + BLo * 4 + bofs, bl0, bl1, bl2, bl3);
            mma16816h(c[2 * ntp + 0], a0, a1, a2, a3, bh0, bh1);
            mma16816h(c[2 * ntp + 0], a0, a1, a2, a3, bl0, bl1);
            mma16816h(c[2 * ntp + 1], a0, a1, a2, a3, bh2, bh3);
            mma16816h(c[2 * ntp + 1], a0, a1, a2, a3, bl2, bl3);
        }
    }
}

// ---------------- preprocess: splits ----------------
__global__ __launch_bounds__(256) void split_f32(const float* __restrict__ src,
                                                 __nv_bfloat16* __restrict__ dh,
                                                 __nv_bfloat16* __restrict__ dl,
                                                 int n2) {
    int i = blockIdx.x * 256 + threadIdx.x;
    if (i < n2) {
        float2 v = reinterpret_cast<const float2*>(src)[i];
        unsigned hi, lo; split2(v.x, v.y, hi, lo);
        reinterpret_cast<unsigned*>(dh)[i] = hi;
        reinterpret_cast<unsigned*>(dl)[i] = lo;
    }
}

__global__ __launch_bounds__(256) void tsplit_w(const float* __restrict__ W,
                                                __nv_bfloat16* __restrict__ dh,
                                                __nv_bfloat16* __restrict__ dl,
                                                int K, int NB) {
    __shared__ float tile[32][33];
    const int n0 = blockIdx.x * 32, k0 = blockIdx.y * 32;
    const int tx = threadIdx.x & 31, ty = threadIdx.x >> 5;
    for (int r = ty; r < 32; r += 8)
        tile[r][tx] = W[(size_t)(k0 + r) * NB + n0 + tx];
    __syncthreads();
    for (int u = threadIdx.x; u < 512; u += 256) {
        const int rr = u >> 4, c = (u & 15) * 2;
        unsigned hi, lo; split2(tile[c][rr], tile[c + 1][rr], hi, lo);
        const size_t off = ((size_t)(n0 + rr) * K + k0 + c) >> 1;
        reinterpret_cast<unsigned*>(dh)[off] = hi;
        reinterpret_cast<unsigned*>(dl)[off] = lo;
    }
}

// ---------------- HMMA GEMM: 128m x 64n, 4 warps @ 64x32, 2-stage ----------
#define SAH 0
#define SAL 4608
#define SBH 9216
#define SBL 11520
#define GSTG 13824

__global__ __launch_bounds__(128, 2) void mma_gemm(
    const __nv_bfloat16* __restrict__ Ah, const __nv_bfloat16* __restrict__ Al,
    const __nv_bfloat16* __restrict__ Bh, const __nv_bfloat16* __restrict__ Bl,
    float* __restrict__ Cout, int mode) {
    extern __shared__ unsigned su[];
    const unsigned sbase = (unsigned)__cvta_generic_to_shared(su);
    const int K = 1024;
    const int m0 = blockIdx.y * 128, n0 = blockIdx.x * 64;
    const int tid = threadIdx.x, lane = tid & 31, wp = tid >> 5;
    const int g = lane >> 2, t = lane & 3;
    const int rg = (wp >> 1) * 64, cg = wp & 1;

    const uint4* pAh = reinterpret_cast<const uint4*>(Ah + (size_t)m0 * K);
    const uint4* pAl = reinterpret_cast<const uint4*>(Al + (size_t)m0 * K);
    const uint4* pBh = reinterpret_cast<const uint4*>(Bh + (size_t)n0 * K);
    const uint4* pBl = reinterpret_cast<const uint4*>(Bl + (size_t)n0 * K);

    float c16[16][4] = {};

#define GLOAD(ST, K0)                                                          \
    {                                                                          \
        const int kc = (K0) >> 3;                                              \
        const unsigned base = sbase + (ST) * (GSTG * 4);                       \
        for (int idx = tid; idx < 2048; idx += 128) {                          \
            const int half = idx >> 10, r = (idx & 1023) >> 3, c = idx & 7;    \
            cpa16(base + (half ? SAL : SAH) * 4 + (r * 9 + c) * 16,            \
                  (half ? pAl : pAh) + (size_t)r * 128 + kc + c);              \
        }                                                                      \
        for (int idx = tid; idx < 1024; idx += 128) {                          \
            const int half = idx >> 9, r = (idx & 511) >> 3, c = idx & 7;      \
            cpa16(base + (half ? SBL : SBH) * 4 + (r * 9 + c) * 16,            \
                  (half ? pBl : pBh) + (size_t)r * 128 + kc + c);              \
        }                                                                      \
        cp_commit();                                                           \
    }

    GLOAD(0, 0)
    for (int it = 0; it < 16; it++) {
        if (it + 1 < 16) { GLOAD((it + 1) & 1, (it + 1) * 64) cp_wait1(); }
        else cp_wait0();
        __syncthreads();
        mma_tile64(sbase + (it & 1) * (GSTG * 4), SAH, SAL, SBH, SBL,
                   rg, cg * 32, lane, c16);
        __syncthreads();
    }
#undef GLOAD

    if (mode == 0) {
        const int part = n0 >> 10;
        const int b = m0 >> 11;
        const int mloc = m0 & (N_ - 1);
        const int hh = (n0 & 1023) >> 6;
        const int bh = b * H_ + hh;
        if (part < 2) {
            const float SCp = (part == 0) ? 0.03125f : 1.0f;
            unsigned* uh = reinterpret_cast<unsigned*>(part == 0 ? g_qh : g_kh);
            unsigned* ul = reinterpret_cast<unsigned*>(part == 0 ? g_ql : g_kl);
#pragma unroll
            for (int mt = 0; mt < 4; mt++)
#pragma unroll
                for (int nt = 0; nt < 4; nt++) {
                    const float* cc = c16[mt * 4 + nt];
                    const int R0 = mloc + rg + mt * 16 + g;
                    const int d = cg * 32 + nt * 8 + 2 * t;
                    unsigned hi, lo;
                    split2(cc[0] * SCp, cc[1] * SCp, hi, lo);
                    const size_t o0 = (((size_t)bh * N_ + R0) * D_ + d) >> 1;
                    uh[o0] = hi; ul[o0] = lo;
                    split2(cc[2] * SCp, cc[3] * SCp, hi, lo);
                    const size_t o1 = (((size_t)bh * N_ + R0 + 8) * D_ + d) >> 1;
                    uh[o1] = hi; ul[o1] = lo;
                }
        } else {
            // V: store fp16 split [bh][d][n]
#pragma unroll
            for (int mt = 0; mt < 4; mt++)
#pragma unroll
                for (int nt = 0; nt < 4; nt++) {
                    const float* cc = c16[mt * 4 + nt];
                    const int i0v = mloc + rg + mt * 16 + g;
                    const int d = cg * 32 + nt * 8 + 2 * t;
                    const size_t b0 = ((size_t)bh * D_ + d) * N_;
                    const size_t b1 = ((size_t)bh * D_ + d + 1) * N_;
#pragma unroll
                    for (int q = 0; q < 4; q++) {
                        const float v = cc[q];
                        const size_t off = ((q & 1) ? b1 : b0) + i0v + (q >> 1) * 8;
                        const __half hb = __float2half(v);
                        g_vh[off] = hb;
                        g_vl[off] = __float2half(v - __half2float(hb));
                    }
                }
        }
    } else {
#pragma unroll
        for (int mt = 0; mt < 4; mt++)
#pragma unroll
            for (int nt = 0; nt < 4; nt++) {
                const float* cc = c16[mt * 4 + nt];
                const int R0 = m0 + rg + mt * 16 + g;
                const int n = n0 + cg * 32 + nt * 8 + 2 * t;
                *reinterpret_cast<float2*>(&Cout[(size_t)R0 * DIM_ + n]) =
                    make_float2(cc[0], cc[1]);
                *reinterpret_cast<float2*>(&Cout[(size_t)(R0 + 8) * DIM_ + n]) =
                    make_float2(cc[2], cc[3]);
            }
    }
}

// ---------------- HMMA segment attention: 256 thr, 8 warps @ m16n64 ---------
// smem words: QH/W 0 (4608), QL 4608 (4608); stages 9216 + s*4608
// (XH +0, XL +2304); dsh 18432 (512 f, in-place inv). 18944 w = 75776 B
#define SQH 0
#define SQL 4608
#define ASST 9216
#define ASDS 18432

#define ACCSEG(DS, SG, E)                                                      \
    { if ((SG) == 0) (DS)[0] += (E); else if ((SG) == 1) (DS)[1] += (E);       \
      else if ((SG) == 2) (DS)[2] += (E); else (DS)[3] += (E); }

__global__ __launch_bounds__(256, 2) void attn_mma(const int* __restrict__ mask) {
    extern __shared__ unsigned su[];
    const unsigned sbase = (unsigned)__cvta_generic_to_shared(su);
    float* dshf = reinterpret_cast<float*>(su + ASDS);
    uint4* su4 = reinterpret_cast<uint4*>(su);

    const int b = blockIdx.z, h = blockIdx.x;
    const int i0 = blockIdx.y * 128;
    const int bh = b * H_ + h;
    const int tid = threadIdx.x;
    const int lane = tid & 31, wp = tid >> 5;
    const int g = lane >> 2, t = lane & 3;
    const int r0 = wp * 16 + g, r1 = r0 + 8;
    const int* mrow = mask + (size_t)b * N_ * N_ + (size_t)i0 * N_;
    unsigned* eblk = g_e + (((size_t)bh * 16 + blockIdx.y) << 17);

    // load Q tile (hi/lo)
    {
        const uint4* gqh = reinterpret_cast<const uint4*>(g_qh + ((size_t)bh * N_ + i0) * D_);
        const uint4* gql = reinterpret_cast<const uint4*>(g_ql + ((size_t)bh * N_ + i0) * D_);
        for (int idx = tid; idx < 1024; idx += 256) {
            const int r = idx >> 3, c = idx & 7;
            su4[(SQH >> 2) + r * 9 + c] = gqh[idx];
            su4[(SQL >> 2) + r * 9 + c] = gql[idx];
        }
    }

    const uint4* gkh = reinterpret_cast<const uint4*>(g_kh + (size_t)bh * N_ * D_);
    const uint4* gkl = reinterpret_cast<const uint4*>(g_kl + (size_t)bh * N_ * D_);
    const uint4* gvh = reinterpret_cast<const uint4*>(g_vh + (size_t)bh * D_ * N_);
    const uint4* gvl = reinterpret_cast<const uint4*>(g_vl + (size_t)bh * D_ * N_);

#define LOADK(ST, JT)                                                          \
    {                                                                          \
        const unsigned base = sbase + (ASST + (ST) * 4608) * 4;                \
        const int jr = (JT) * 512;                                             \
        for (int idx = tid; idx < 1024; idx += 256) {                          \
            const int half = idx >> 9, r = (idx & 511) >> 3, c = idx & 7;      \
            cpa16(base + half * 9216 + (r * 9 + c) * 16,                       \
                  (half ? gkl : gkh) + jr + (size_t)r * 8 + c);                \
        }                                                                      \
        cp_commit();                                                           \
    }
#define LOADV(ST, JT)                                                          \
    {                                                                          \
        const unsigned base = sbase + (ASST + (ST) * 4608) * 4;                \
        const int jc = (JT) * 8;                                               \
        for (int idx = tid; idx < 1024; idx += 256) {                          \
            const int half = idx >> 9, r = (idx & 511) >> 3, c = idx & 7;      \
            cpa16(base + half * 9216 + (r * 9 + c) * 16,                       \
                  (half ? gvl : gvh) + (size_t)r * 256 + jc + c);              \
        }                                                                      \
        cp_commit();                                                           \
    }

    // ---------------- PASS 1: denominators + e store (fp16x2) ----------------
    float ds0[4] = {0.f, 0.f, 0.f, 0.f}, ds1[4] = {0.f, 0.f, 0.f, 0.f};
    LOADK(0, 0)
    for (int jt = 0; jt < 32; jt++) {
        if (jt + 1 < 32) { LOADK((jt + 1) & 1, jt + 1) cp_wait1(); }
        else cp_wait0();
        __syncthreads();
        const int koff = ASST + (jt & 1) * 4608;
        float c8[8][4] = {};
        mma_tile(sbase, SQH, SQL, koff, koff + 2304, wp * 16, lane, c8);
        __syncthreads();
        unsigned* ew = eblk + ((size_t)jt * 8 + wp) * 512;
        const int j0 = jt * 64;
#pragma unroll
        for (int nt = 0; nt < 8; nt++) {
            const int jc = j0 + nt * 8 + 2 * t;
            const int2 m0 = *reinterpret_cast<const int2*>(&mrow[(size_t)r0 * N_ + jc]);
            const int2 m1 = *reinterpret_cast<const int2*>(&mrow[(size_t)r1 * N_ + jc]);
            const float e0 = __expf(c8[nt][0]), e1 = __expf(c8[nt][1]);
            const float e2 = __expf(c8[nt][2]), e3 = __expf(c8[nt][3]);
            ACCSEG(ds0, m0.x, e0) ACCSEG(ds0, m0.y, e1)
            ACCSEG(ds1, m1.x, e2) ACCSEG(ds1, m1.y, e3)
            ew[nt * 64 + lane] = packf16(e0, e1);
            ew[nt * 64 + 32 + lane] = packf16(e2, e3);
        }
    }
#pragma unroll
    for (int s = 0; s < 4; s++) {
        float v0 = ds0[s], v1 = ds1[s];
        v0 += __shfl_xor_sync(0xffffffffu, v0, 1);
        v0 += __shfl_xor_sync(0xffffffffu, v0, 2);
        v1 += __shfl_xor_sync(0xffffffffu, v1, 1);
        v1 += __shfl_xor_sync(0xffffffffu, v1, 2);
        if (t == 0) { dshf[r0 * 4 + s] = v0; dshf[r1 * 4 + s] = v1; }
    }
    __syncthreads();
    for (int idx = tid; idx < 512; idx += 256) {
        const float dv = dshf[idx];
        dshf[idx] = (dv == 0.0f) ? 1.0f : 1.0f / dv;
    }
    __syncthreads();

    // ---------------- PASS 2: w(fp16) = e*invd -> O += w @ V ----------------
    float o8[8][4] = {};
    LOADV(0, 0)
    for (int jt = 0; jt < 32; jt++) {
        if (jt + 1 < 32) LOADV((jt + 1) & 1, jt + 1)
        const unsigned* ew = eblk + ((size_t)jt * 8 + wp) * 512;
        const int j0 = jt * 64;
#pragma unroll
        for (int nt = 0; nt < 8; nt++) {
            const int jc = j0 + nt * 8 + 2 * t;
            const int2 m0 = *reinterpret_cast<const int2*>(&mrow[(size_t)r0 * N_ + jc]);
            const int2 m1 = *reinterpret_cast<const int2*>(&mrow[(size_t)r1 * N_ + jc]);
            const unsigned uA = ew[nt * 64 + lane];
            const unsigned uB = ew[nt * 64 + 32 + lane];
            const float2 eA = __half22float2(*reinterpret_cast<const __half2*>(&uA));
            const float2 eB = __half22float2(*reinterpret_cast<const __half2*>(&uB));
            su[SQH + r0 * 36 + nt * 4 + t] =
                packf16(eA.x * dshf[r0 * 4 + m0.x], eA.y * dshf[r0 * 4 + m0.y]);
            su[SQH + r1 * 36 + nt * 4 + t] =
                packf16(eB.x * dshf[r1 * 4 + m1.x], eB.y * dshf[r1 * 4 + m1.y]);
        }
        if (jt + 1 < 32) cp_wait1(); else cp_wait0();
        __syncthreads();
        const int voff = ASST + (jt & 1) * 4608;
        mma_tile_w(sbase, SQH, voff, voff + 2304, wp * 16, lane, o8);
        __syncthreads();
    }
#undef LOADK
#undef LOADV

    // store O as split bf16
    {
        unsigned* ah = reinterpret_cast<unsigned*>(g_ah);
        unsigned* al = reinterpret_cast<unsigned*>(g_al);
#pragma unroll
        for (int nt = 0; nt < 8; nt++) {
            const int d = h * 64 + nt * 8 + 2 * t;
            unsigned hi, lo;
            split2(o8[nt][0], o8[nt][1], hi, lo);
            const size_t o0 = ((size_t)(b * N_ + i0 + r0) * DIM_ + d) >> 1;
            ah[o0] = hi; al[o0] = lo;
            split2(o8[nt][2], o8[nt][3], hi, lo);
            const size_t o1 = ((size_t)(b * N_ + i0 + r1) * DIM_ + d) >> 1;
            ah[o1] = hi; al[o1] = lo;
        }
    }
}

// ---------------------------------------------------------------------------
extern "C" void kernel_launch(void* const* d_in, const int* in_sizes, int n_in,
                              void* d_out, int out_size) {
    const float* features = (const float*)d_in[0];
    const int*   mask     = (const int*)d_in[1];
    const float* W_qkv    = (const float*)d_in[2];
    const float* W_out    = (const float*)d_in[3];
    float* out = (float*)d_out;

    cudaFuncSetAttribute(attn_mma, cudaFuncAttributeMaxDynamicSharedMemorySize, 75776);
    cudaFuncSetAttribute(mma_gemm, cudaFuncAttributeMaxDynamicSharedMemorySize, 110592);

    __nv_bfloat16 *fh, *fl, *wqh, *wql, *woh, *wol, *ah, *al;
    cudaGetSymbolAddress((void**)&fh, g_fh);   cudaGetSymbolAddress((void**)&fl, g_fl);
    cudaGetSymbolAddress((void**)&wqh, g_wqh); cudaGetSymbolAddress((void**)&wql, g_wql);
    cudaGetSymbolAddress((void**)&woh, g_woh); cudaGetSymbolAddress((void**)&wol, g_wol);
    cudaGetSymbolAddress((void**)&ah, g_ah);   cudaGetSymbolAddress((void**)&al, g_al);

    split_f32<<<(M_ * DIM_ / 2 + 255) / 256, 256>>>(features, fh, fl, M_ * DIM_ / 2);
    tsplit_w<<<dim3(3 * DIM_ / 32, DIM_ / 32), 256>>>(W_qkv, wqh, wql, DIM_, 3 * DIM_);
    tsplit_w<<<dim3(DIM_ / 32, DIM_ / 32), 256>>>(W_out, woh, wol, DIM_, DIM_);

    mma_gemm<<<dim3(3 * DIM_ / 64, M_ / 128), 128, 110592>>>(fh, fl, wqh, wql, nullptr, 0);
    attn_mma<<<dim3(H_, N_ / 128, B_), 256, 75776>>>(mask);
    mma_gemm<<<dim3(DIM_ / 64, M_ / 128), 128, 110592>>>(ah, al, woh, wol, out, 1);
}

// round 14
// speedup vs baseline: 1.5183x; 1.0629x over previous
#include <cuda_runtime.h>
#include <cuda_bf16.h>
#include <cuda_fp16.h>
#include <cstdint>

#define B_   2
#define N_   2048
#define DIM_ 1024
#define H_   16
#define D_   64
#define BH_  (B_ * H_)
#define M_   (B_ * N_)

// ---- device scratch (allocation-free rule) ----
__device__ __nv_bfloat16 g_fh[(size_t)M_ * DIM_];
__device__ __nv_bfloat16 g_fl[(size_t)M_ * DIM_];
__device__ __nv_bfloat16 g_wqh[(size_t)3 * DIM_ * DIM_];
__device__ __nv_bfloat16 g_wql[(size_t)3 * DIM_ * DIM_];
__device__ __nv_bfloat16 g_woh[(size_t)DIM_ * DIM_];
__device__ __nv_bfloat16 g_wol[(size_t)DIM_ * DIM_];
__device__ __half g_q[(size_t)BH_ * N_ * D_];         // q/32, fp16
__device__ __half g_k[(size_t)BH_ * N_ * D_];         // k, fp16
__device__ __half g_v[(size_t)BH_ * D_ * N_];         // v transposed, fp16
__device__ __nv_bfloat16 g_ah[(size_t)M_ * DIM_];
__device__ __nv_bfloat16 g_al[(size_t)M_ * DIM_];
__device__ unsigned g_e[(size_t)BH_ * N_ * N_ / 2];   // exp(scores) fp16x2

__device__ __forceinline__ unsigned b2u(__nv_bfloat162 v) {
    return *reinterpret_cast<unsigned*>(&v);
}
__device__ __forceinline__ void split2(float x0, float x1, unsigned& hi, unsigned& lo) {
    __nv_bfloat162 h2 = __floats2bfloat162_rn(x0, x1);
    __nv_bfloat162 l2 = __floats2bfloat162_rn(x0 - __bfloat162float(h2.x),
                                              x1 - __bfloat162float(h2.y));
    hi = b2u(h2); lo = b2u(l2);
}

__device__ __forceinline__ void mma16816(float* c, unsigned a0, unsigned a1,
                                         unsigned a2, unsigned a3,
                                         unsigned b0, unsigned b1) {
    asm("mma.sync.aligned.m16n8k16.row.col.f32.bf16.bf16.f32 "
        "{%0,%1,%2,%3},{%4,%5,%6,%7},{%8,%9},{%0,%1,%2,%3};\n"
        : "+f"(c[0]), "+f"(c[1]), "+f"(c[2]), "+f"(c[3])
        : "r"(a0), "r"(a1), "r"(a2), "r"(a3), "r"(b0), "r"(b1));
}
__device__ __forceinline__ void mma16816h(float* c, unsigned a0, unsigned a1,
                                          unsigned a2, unsigned a3,
                                          unsigned b0, unsigned b1) {
    asm("mma.sync.aligned.m16n8k16.row.col.f32.f16.f16.f32 "
        "{%0,%1,%2,%3},{%4,%5,%6,%7},{%8,%9},{%0,%1,%2,%3};\n"
        : "+f"(c[0]), "+f"(c[1]), "+f"(c[2]), "+f"(c[3])
        : "r"(a0), "r"(a1), "r"(a2), "r"(a3), "r"(b0), "r"(b1));
}

__device__ __forceinline__ void ldsm4(unsigned addr, unsigned& r0, unsigned& r1,
                                      unsigned& r2, unsigned& r3) {
    asm volatile("ldmatrix.sync.aligned.m8n8.x4.shared.b16 {%0,%1,%2,%3}, [%4];\n"
                 : "=r"(r0), "=r"(r1), "=r"(r2), "=r"(r3) : "r"(addr));
}

__device__ __forceinline__ void cpa16(unsigned dst, const void* src) {
    asm volatile("cp.async.cg.shared.global [%0], [%1], 16;\n" :: "r"(dst), "l"(src));
}
__device__ __forceinline__ void cp_commit() { asm volatile("cp.async.commit_group;\n"); }
__device__ __forceinline__ void cp_wait1() { asm volatile("cp.async.wait_group 1;\n"); }
__device__ __forceinline__ void cp_wait0() { asm volatile("cp.async.wait_group 0;\n"); }

__device__ __forceinline__ unsigned packf16(float lo, float hi) {
    unsigned u;
    asm("cvt.rn.f16x2.f32 %0, %1, %2;" : "=r"(u) : "f"(hi), "f"(lo));
    return u;
}

// ---------------------------------------------------------------------------
// m64 x n32 x k64 warp-tile block-MMA (GEMM), bf16 hi/lo split, stride 36 w.
// ---------------------------------------------------------------------------
__device__ __forceinline__ void mma_tile64(unsigned sb, int AH, int AL,
                                           int BHo, int BLo, int arow, int bcol,
                                           int lane, float c[16][4]) {
    const int m = lane >> 3, r = lane & 7;
    const unsigned paw = (unsigned)((arow + (m & 1) * 8 + r) * 36 + (m >> 1) * 4) * 4;
    const unsigned pbw = (unsigned)((bcol + (m >> 1) * 8 + r) * 36 + (m & 1) * 4) * 4;
#pragma unroll
    for (int ks = 0; ks < 4; ks++) {
        unsigned ah[4][4], al_[4][4];
#pragma unroll
        for (int mt = 0; mt < 4; mt++) {
            ldsm4(sb + AH * 4 + paw + mt * (16 * 36 * 4) + ks * 32,
                  ah[mt][0], ah[mt][1], ah[mt][2], ah[mt][3]);
            ldsm4(sb + AL * 4 + paw + mt * (16 * 36 * 4) + ks * 32,
                  al_[mt][0], al_[mt][1], al_[mt][2], al_[mt][3]);
        }
#pragma unroll
        for (int np = 0; np < 2; np++) {
            unsigned bh[4], bl[4];
            ldsm4(sb + BHo * 4 + pbw + np * (16 * 36 * 4) + ks * 32,
                  bh[0], bh[1], bh[2], bh[3]);
            ldsm4(sb + BLo * 4 + pbw + np * (16 * 36 * 4) + ks * 32,
                  bl[0], bl[1], bl[2], bl[3]);
#pragma unroll
            for (int mt = 0; mt < 4; mt++) {
                float* c0 = c[mt * 4 + np * 2 + 0];
                float* c1 = c[mt * 4 + np * 2 + 1];
                mma16816(c0, ah[mt][0], ah[mt][1], ah[mt][2], ah[mt][3], bh[0], bh[1]);
                mma16816(c0, ah[mt][0], ah[mt][1], ah[mt][2], ah[mt][3], bl[0], bl[1]);
                mma16816(c0, al_[mt][0], al_[mt][1], al_[mt][2], al_[mt][3], bh[0], bh[1]);
                mma16816(c1, ah[mt][0], ah[mt][1], ah[mt][2], ah[mt][3], bh[2], bh[3]);
                mma16816(c1, ah[mt][0], ah[mt][1], ah[mt][2], ah[mt][3], bl[2], bl[3]);
                mma16816(c1, al_[mt][0], al_[mt][1], al_[mt][2], al_[mt][3], bh[2], bh[3]);
            }
        }
    }
}

// m16 x n64 x k64 warp-tile, single fp16 A and B, stride 36 words.
__device__ __forceinline__ void mma_tile_h(unsigned sb, int A, int Bo,
                                           int arow, int lane, float c[8][4]) {
    const int m = lane >> 3, r = lane & 7;
    const unsigned pa = ((unsigned)(arow + (m & 1) * 8 + r) * 36 + (m >> 1) * 4) * 4;
    const unsigned pb = (((unsigned)((m >> 1) * 8 + r)) * 36 + (m & 1) * 4) * 4;
#pragma unroll
    for (int ks = 0; ks < 4; ks++) {
        unsigned a0, a1, a2, a3;
        ldsm4(sb + A * 4 + pa + ks * 32, a0, a1, a2, a3);
#pragma unroll
        for (int ntp = 0; ntp < 4; ntp++) {
            unsigned b0, b1, b2, b3;
            ldsm4(sb + Bo * 4 + pb + ntp * (16 * 36 * 4) + ks * 32, b0, b1, b2, b3);
            mma16816h(c[2 * ntp + 0], a0, a1, a2, a3, b0, b1);
            mma16816h(c[2 * ntp + 1], a0, a1, a2, a3, b2, b3);
        }
    }
}

// ---------------- preprocess: splits ----------------
__global__ __launch_bounds__(256) void split_f32(const float* __restrict__ src,
                                                 __nv_bfloat16* __restrict__ dh,
                                                 __nv_bfloat16* __restrict__ dl,
                                                 int n2) {
    int i = blockIdx.x * 256 + threadIdx.x;
    if (i < n2) {
        float2 v = reinterpret_cast<const float2*>(src)[i];
        unsigned hi, lo; split2(v.x, v.y, hi, lo);
        reinterpret_cast<unsigned*>(dh)[i] = hi;
        reinterpret_cast<unsigned*>(dl)[i] = lo;
    }
}

__global__ __launch_bounds__(256) void tsplit_w(const float* __restrict__ W,
                                                __nv_bfloat16* __restrict__ dh,
                                                __nv_bfloat16* __restrict__ dl,
                                                int K, int NB) {
    __shared__ float tile[32][33];
    const int n0 = blockIdx.x * 32, k0 = blockIdx.y * 32;
    const int tx = threadIdx.x & 31, ty = threadIdx.x >> 5;
    for (int r = ty; r < 32; r += 8)
        tile[r][tx] = W[(size_t)(k0 + r) * NB + n0 + tx];
    __syncthreads();
    for (int u = threadIdx.x; u < 512; u += 256) {
        const int rr = u >> 4, c = (u & 15) * 2;
        unsigned hi, lo; split2(tile[c][rr], tile[c + 1][rr], hi, lo);
        const size_t off = ((size_t)(n0 + rr) * K + k0 + c) >> 1;
        reinterpret_cast<unsigned*>(dh)[off] = hi;
        reinterpret_cast<unsigned*>(dl)[off] = lo;
    }
}

// ---------------- HMMA GEMM: 128m x 64n, 4 warps @ 64x32, 2-stage ----------
#define SAH 0
#define SAL 4608
#define SBH 9216
#define SBL 11520
#define GSTG 13824

__global__ __launch_bounds__(128, 2) void mma_gemm(
    const __nv_bfloat16* __restrict__ Ah, const __nv_bfloat16* __restrict__ Al,
    const __nv_bfloat16* __restrict__ Bh, const __nv_bfloat16* __restrict__ Bl,
    float* __restrict__ Cout, int mode) {
    extern __shared__ unsigned su[];
    const unsigned sbase = (unsigned)__cvta_generic_to_shared(su);
    const int K = 1024;
    const int m0 = blockIdx.y * 128, n0 = blockIdx.x * 64;
    const int tid = threadIdx.x, lane = tid & 31, wp = tid >> 5;
    const int g = lane >> 2, t = lane & 3;
    const int rg = (wp >> 1) * 64, cg = wp & 1;

    const uint4* pAh = reinterpret_cast<const uint4*>(Ah + (size_t)m0 * K);
    const uint4* pAl = reinterpret_cast<const uint4*>(Al + (size_t)m0 * K);
    const uint4* pBh = reinterpret_cast<const uint4*>(Bh + (size_t)n0 * K);
    const uint4* pBl = reinterpret_cast<const uint4*>(Bl + (size_t)n0 * K);

    float c16[16][4] = {};

#define GLOAD(ST, K0)                                                          \
    {                                                                          \
        const int kc = (K0) >> 3;                                              \
        const unsigned base = sbase + (ST) * (GSTG * 4);                       \
        for (int idx = tid; idx < 2048; idx += 128) {                          \
            const int half = idx >> 10, r = (idx & 1023) >> 3, c = idx & 7;    \
            cpa16(base + (half ? SAL : SAH) * 4 + (r * 9 + c) * 16,            \
                  (half ? pAl : pAh) + (size_t)r * 128 + kc + c);              \
        }                                                                      \
        for (int idx = tid; idx < 1024; idx += 128) {                          \
            const int half = idx >> 9, r = (idx & 511) >> 3, c = idx & 7;      \
            cpa16(base + (half ? SBL : SBH) * 4 + (r * 9 + c) * 16,            \
                  (half ? pBl : pBh) + (size_t)r * 128 + kc + c);              \
        }                                                                      \
        cp_commit();                                                           \
    }

    GLOAD(0, 0)
    for (int it = 0; it < 16; it++) {
        if (it + 1 < 16) { GLOAD((it + 1) & 1, (it + 1) * 64) cp_wait1(); }
        else cp_wait0();
        __syncthreads();
        mma_tile64(sbase + (it & 1) * (GSTG * 4), SAH, SAL, SBH, SBL,
                   rg, cg * 32, lane, c16);
        __syncthreads();
    }
#undef GLOAD

    if (mode == 0) {
        const int part = n0 >> 10;
        const int b = m0 >> 11;
        const int mloc = m0 & (N_ - 1);
        const int hh = (n0 & 1023) >> 6;
        const int bh = b * H_ + hh;
        if (part < 2) {
            // q/k: single fp16, packed pairs
            const float SCp = (part == 0) ? 0.03125f : 1.0f;
            unsigned* uq = reinterpret_cast<unsigned*>(part == 0 ? g_q : g_k);
#pragma unroll
            for (int mt = 0; mt < 4; mt++)
#pragma unroll
                for (int nt = 0; nt < 4; nt++) {
                    const float* cc = c16[mt * 4 + nt];
                    const int R0 = mloc + rg + mt * 16 + g;
                    const int d = cg * 32 + nt * 8 + 2 * t;
                    uq[(((size_t)bh * N_ + R0) * D_ + d) >> 1] =
                        packf16(cc[0] * SCp, cc[1] * SCp);
                    uq[(((size_t)bh * N_ + R0 + 8) * D_ + d) >> 1] =
                        packf16(cc[2] * SCp, cc[3] * SCp);
                }
        } else {
            // V: single fp16, [bh][d][n]
#pragma unroll
            for (int mt = 0; mt < 4; mt++)
#pragma unroll
                for (int nt = 0; nt < 4; nt++) {
                    const float* cc = c16[mt * 4 + nt];
                    const int i0v = mloc + rg + mt * 16 + g;
                    const int d = cg * 32 + nt * 8 + 2 * t;
                    const size_t b0 = ((size_t)bh * D_ + d) * N_;
                    const size_t b1 = ((size_t)bh * D_ + d + 1) * N_;
                    g_v[b0 + i0v] = __float2half(cc[0]);
                    g_v[b1 + i0v] = __float2half(cc[1]);
                    g_v[b0 + i0v + 8] = __float2half(cc[2]);
                    g_v[b1 + i0v + 8] = __float2half(cc[3]);
                }
        }
    } else {
#pragma unroll
        for (int mt = 0; mt < 4; mt++)
#pragma unroll
            for (int nt = 0; nt < 4; nt++) {
                const float* cc = c16[mt * 4 + nt];
                const int R0 = m0 + rg + mt * 16 + g;
                const int n = n0 + cg * 32 + nt * 8 + 2 * t;
                *reinterpret_cast<float2*>(&Cout[(size_t)R0 * DIM_ + n]) =
                    make_float2(cc[0], cc[1]);
                *reinterpret_cast<float2*>(&Cout[(size_t)(R0 + 8) * DIM_ + n]) =
                    make_float2(cc[2], cc[3]);
            }
    }
}

// ---------------- HMMA segment attention: 256 thr, 8 warps @ m16n64 ---------
// fp16 everywhere. smem words: SQ (Q, reused as W) 0..4608;
// stages: ASST + s*2304 (2 stages of K or V, 64 rows x 36 w);
// dsh 9216 (512 f). total 9728 w = 38912 B
#define SQ   0
#define ASST 4608
#define ASDS 9216

#define ACCSEG(DS, SG, E)                                                      \
    { if ((SG) == 0) (DS)[0] += (E); else if ((SG) == 1) (DS)[1] += (E);       \
      else if ((SG) == 2) (DS)[2] += (E); else (DS)[3] += (E); }

__global__ __launch_bounds__(256, 2) void attn_mma(const int* __restrict__ mask) {
    extern __shared__ unsigned su[];
    const unsigned sbase = (unsigned)__cvta_generic_to_shared(su);
    float* dshf = reinterpret_cast<float*>(su + ASDS);
    uint4* su4 = reinterpret_cast<uint4*>(su);

    const int b = blockIdx.z, h = blockIdx.x;
    const int i0 = blockIdx.y * 128;
    const int bh = b * H_ + h;
    const int tid = threadIdx.x;
    const int lane = tid & 31, wp = tid >> 5;
    const int g = lane >> 2, t = lane & 3;
    const int r0 = wp * 16 + g, r1 = r0 + 8;
    const int* mrow = mask + (size_t)b * N_ * N_ + (size_t)i0 * N_;
    unsigned* eblk = g_e + (((size_t)bh * 16 + blockIdx.y) << 17);

    // load Q tile (fp16, 128 rows x 8 uint4)
    {
        const uint4* gq = reinterpret_cast<const uint4*>(g_q + ((size_t)bh * N_ + i0) * D_);
        for (int idx = tid; idx < 1024; idx += 256) {
            const int r = idx >> 3, c = idx & 7;
            su4[(SQ >> 2) + r * 9 + c] = gq[idx];
        }
    }

    const uint4* gk = reinterpret_cast<const uint4*>(g_k + (size_t)bh * N_ * D_);
    const uint4* gv = reinterpret_cast<const uint4*>(g_v + (size_t)bh * D_ * N_);

#define LOADK(ST, JT)                                                          \
    {                                                                          \
        const unsigned base = sbase + (ASST + (ST) * 2304) * 4;                \
        const int jr = (JT) * 512;                                             \
        for (int idx = tid; idx < 512; idx += 256) {                           \
            const int r = idx >> 3, c = idx & 7;                               \
            cpa16(base + (r * 9 + c) * 16, gk + jr + (size_t)r * 8 + c);       \
        }                                                                      \
        cp_commit();                                                           \
    }
#define LOADV(ST, JT)                                                          \
    {                                                                          \
        const unsigned base = sbase + (ASST + (ST) * 2304) * 4;                \
        const int jc = (JT) * 8;                                               \
        for (int idx = tid; idx < 512; idx += 256) {                           \
            const int r = idx >> 3, c = idx & 7;                               \
            cpa16(base + (r * 9 + c) * 16, gv + (size_t)r * 256 + jc + c);     \
        }                                                                      \
        cp_commit();                                                           \
    }

    // ---------------- PASS 1: denominators + e store (fp16x2) ----------------
    float ds0[4] = {0.f, 0.f, 0.f, 0.f}, ds1[4] = {0.f, 0.f, 0.f, 0.f};
    LOADK(0, 0)
    for (int jt = 0; jt < 32; jt++) {
        if (jt + 1 < 32) { LOADK((jt + 1) & 1, jt + 1) cp_wait1(); }
        else cp_wait0();
        __syncthreads();
        const int koff = ASST + (jt & 1) * 2304;
        float c8[8][4] = {};
        mma_tile_h(sbase, SQ, koff, wp * 16, lane, c8);
        __syncthreads();
        unsigned* ew = eblk + ((size_t)jt * 8 + wp) * 512;
        const int j0 = jt * 64;
#pragma unroll
        for (int nt = 0; nt < 8; nt++) {
            const int jc = j0 + nt * 8 + 2 * t;
            const int2 m0 = *reinterpret_cast<const int2*>(&mrow[(size_t)r0 * N_ + jc]);
            const int2 m1 = *reinterpret_cast<const int2*>(&mrow[(size_t)r1 * N_ + jc]);
            const float e0 = __expf(c8[nt][0]), e1 = __expf(c8[nt][1]);
            const float e2 = __expf(c8[nt][2]), e3 = __expf(c8[nt][3]);
            ACCSEG(ds0, m0.x, e0) ACCSEG(ds0, m0.y, e1)
            ACCSEG(ds1, m1.x, e2) ACCSEG(ds1, m1.y, e3)
            ew[nt * 64 + lane] = packf16(e0, e1);
            ew[nt * 64 + 32 + lane] = packf16(e2, e3);
        }
    }
#pragma unroll
    for (int s = 0; s < 4; s++) {
        float v0 = ds0[s], v1 = ds1[s];
        v0 += __shfl_xor_sync(0xffffffffu, v0, 1);
        v0 += __shfl_xor_sync(0xffffffffu, v0, 2);
        v1 += __shfl_xor_sync(0xffffffffu, v1, 1);
        v1 += __shfl_xor_sync(0xffffffffu, v1, 2);
        if (t == 0) { dshf[r0 * 4 + s] = v0; dshf[r1 * 4 + s] = v1; }
    }
    __syncthreads();
    for (int idx = tid; idx < 512; idx += 256) {
        const float dv = dshf[idx];
        dshf[idx] = (dv == 0.0f) ? 1.0f : 1.0f / dv;
    }
    __syncthreads();

    // ---------------- PASS 2: w(fp16, in SQ) = e*invd -> O += w @ V ----------
    float o8[8][4] = {};
    LOADV(0, 0)
    for (int jt = 0; jt < 32; jt++) {
        if (jt + 1 < 32) LOADV((jt + 1) & 1, jt + 1)
        const unsigned* ew = eblk + ((size_t)jt * 8 + wp) * 512;
        const int j0 = jt * 64;
#pragma unroll
        for (int nt = 0; nt < 8; nt++) {
            const int jc = j0 + nt * 8 + 2 * t;
            const int2 m0 = *reinterpret_cast<const int2*>(&mrow[(size_t)r0 * N_ + jc]);
            const int2 m1 = *reinterpret_cast<const int2*>(&mrow[(size_t)r1 * N_ + jc]);
            const unsigned uA = ew[nt * 64 + lane];
            const unsigned uB = ew[nt * 64 + 32 + lane];
            const float2 eA = __half22float2(*reinterpret_cast<const __half2*>(&uA));
            const float2 eB = __half22float2(*reinterpret_cast<const __half2*>(&uB));
            su[SQ + r0 * 36 + nt * 4 + t] =
                packf16(eA.x * dshf[r0 * 4 + m0.x], eA.y * dshf[r0 * 4 + m0.y]);
            su[SQ + r1 * 36 + nt * 4 + t] =
                packf16(eB.x * dshf[r1 * 4 + m1.x], eB.y * dshf[r1 * 4 + m1.y]);
        }
        if (jt + 1 < 32) cp_wait1(); else cp_wait0();
        __syncthreads();
        const int voff = ASST + (jt & 1) * 2304;
        mma_tile_h(sbase, SQ, voff, wp * 16, lane, o8);
        __syncthreads();
    }
#undef LOADK
#undef LOADV

    // store O as split bf16
    {
        unsigned* ah = reinterpret_cast<unsigned*>(g_ah);
        unsigned* al = reinterpret_cast<unsigned*>(g_al);
#pragma unroll
        for (int nt = 0; nt < 8; nt++) {
            const int d = h * 64 + nt * 8 + 2 * t;
            unsigned hi, lo;
            split2(o8[nt][0], o8[nt][1], hi, lo);
            const size_t o0 = ((size_t)(b * N_ + i0 + r0) * DIM_ + d) >> 1;
            ah[o0] = hi; al[o0] = lo;
            split2(o8[nt][2], o8[nt][3], hi, lo);
            const size_t o1 = ((size_t)(b * N_ + i0 + r1) * DIM_ + d) >> 1;
            ah[o1] = hi; al[o1] = lo;
        }
    }
}

// ---------------------------------------------------------------------------
extern "C" void kernel_launch(void* const* d_in, const int* in_sizes, int n_in,
                              void* d_out, int out_size) {
    const float* features = (const float*)d_in[0];
    const int*   mask     = (const int*)d_in[1];
    const float* W_qkv    = (const float*)d_in[2];
    const float* W_out    = (const float*)d_in[3];
    float* out = (float*)d_out;

    cudaFuncSetAttribute(attn_mma, cudaFuncAttributeMaxDynamicSharedMemorySize, 38912);
    cudaFuncSetAttribute(mma_gemm, cudaFuncAttributeMaxDynamicSharedMemorySize, 110592);

    __nv_bfloat16 *fh, *fl, *wqh, *wql, *woh, *wol, *ah, *al;
    cudaGetSymbolAddress((void**)&fh, g_fh);   cudaGetSymbolAddress((void**)&fl, g_fl);
    cudaGetSymbolAddress((void**)&wqh, g_wqh); cudaGetSymbolAddress((void**)&wql, g_wql);
    cudaGetSymbolAddress((void**)&woh, g_woh); cudaGetSymbolAddress((void**)&wol, g_wol);
    cudaGetSymbolAddress((void**)&ah, g_ah);   cudaGetSymbolAddress((void**)&al, g_al);

    split_f32<<<(M_ * DIM_ / 2 + 255) / 256, 256>>>(features, fh, fl, M_ * DIM_ / 2);
    tsplit_w<<<dim3(3 * DIM_ / 32, DIM_ / 32), 256>>>(W_qkv, wqh, wql, DIM_, 3 * DIM_);
    tsplit_w<<<dim3(DIM_ / 32, DIM_ / 32), 256>>>(W_out, woh, wol, DIM_, DIM_);

    mma_gemm<<<dim3(3 * DIM_ / 64, M_ / 128), 128, 110592>>>(fh, fl, wqh, wql, nullptr, 0);
    attn_mma<<<dim3(H_, N_ / 128, B_), 256, 38912>>>(mask);
    mma_gemm<<<dim3(DIM_ / 64, M_ / 128), 128, 110592>>>(ah, al, woh, wol, out, 1);
}

// round 15
// speedup vs baseline: 2.1985x; 1.4480x over previous
#include <cuda_runtime.h>
#include <cuda_bf16.h>
#include <cuda_fp16.h>
#include <cstdint>

#define B_   2
#define N_   2048
#define DIM_ 1024
#define H_   16
#define D_   64
#define BH_  (B_ * H_)
#define M_   (B_ * N_)

// ---- device scratch (allocation-free rule) ----
__device__ __nv_bfloat16 g_fh[(size_t)M_ * DIM_];
__device__ __nv_bfloat16 g_fl[(size_t)M_ * DIM_];
__device__ __half        g_f16[(size_t)M_ * DIM_];
__device__ __nv_bfloat16 g_wqh[(size_t)3 * DIM_ * DIM_];
__device__ __nv_bfloat16 g_wql[(size_t)3 * DIM_ * DIM_];
__device__ __half        g_wq16[(size_t)3 * DIM_ * DIM_];
__device__ __nv_bfloat16 g_woh[(size_t)DIM_ * DIM_];
__device__ __nv_bfloat16 g_wol[(size_t)DIM_ * DIM_];
__device__ __half g_q[(size_t)BH_ * N_ * D_];         // q/32, fp16
__device__ __half g_k[(size_t)BH_ * N_ * D_];         // k, fp16
__device__ __half g_v[(size_t)BH_ * D_ * N_];         // v transposed, fp16
__device__ __nv_bfloat16 g_ah[(size_t)M_ * DIM_];
__device__ __nv_bfloat16 g_al[(size_t)M_ * DIM_];
__device__ unsigned g_e[(size_t)BH_ * N_ * N_ / 2];   // exp(scores) fp16x2
__device__ unsigned g_mp[(size_t)B_ * N_ * N_ / 16];  // mask packed 2-bit

__device__ __forceinline__ unsigned b2u(__nv_bfloat162 v) {
    return *reinterpret_cast<unsigned*>(&v);
}
__device__ __forceinline__ void split2(float x0, float x1, unsigned& hi, unsigned& lo) {
    __nv_bfloat162 h2 = __floats2bfloat162_rn(x0, x1);
    __nv_bfloat162 l2 = __floats2bfloat162_rn(x0 - __bfloat162float(h2.x),
                                              x1 - __bfloat162float(h2.y));
    hi = b2u(h2); lo = b2u(l2);
}

__device__ __forceinline__ void mma16816(float* c, unsigned a0, unsigned a1,
                                         unsigned a2, unsigned a3,
                                         unsigned b0, unsigned b1) {
    asm("mma.sync.aligned.m16n8k16.row.col.f32.bf16.bf16.f32 "
        "{%0,%1,%2,%3},{%4,%5,%6,%7},{%8,%9},{%0,%1,%2,%3};\n"
        : "+f"(c[0]), "+f"(c[1]), "+f"(c[2]), "+f"(c[3])
        : "r"(a0), "r"(a1), "r"(a2), "r"(a3), "r"(b0), "r"(b1));
}
__device__ __forceinline__ void mma16816h(float* c, unsigned a0, unsigned a1,
                                          unsigned a2, unsigned a3,
                                          unsigned b0, unsigned b1) {
    asm("mma.sync.aligned.m16n8k16.row.col.f32.f16.f16.f32 "
        "{%0,%1,%2,%3},{%4,%5,%6,%7},{%8,%9},{%0,%1,%2,%3};\n"
        : "+f"(c[0]), "+f"(c[1]), "+f"(c[2]), "+f"(c[3])
        : "r"(a0), "r"(a1), "r"(a2), "r"(a3), "r"(b0), "r"(b1));
}

__device__ __forceinline__ void ldsm4(unsigned addr, unsigned& r0, unsigned& r1,
                                      unsigned& r2, unsigned& r3) {
    asm volatile("ldmatrix.sync.aligned.m8n8.x4.shared.b16 {%0,%1,%2,%3}, [%4];\n"
                 : "=r"(r0), "=r"(r1), "=r"(r2), "=r"(r3) : "r"(addr));
}

__device__ __forceinline__ void cpa16(unsigned dst, const void* src) {
    asm volatile("cp.async.cg.shared.global [%0], [%1], 16;\n" :: "r"(dst), "l"(src));
}
__device__ __forceinline__ void cp_commit() { asm volatile("cp.async.commit_group;\n"); }
__device__ __forceinline__ void cp_wait1() { asm volatile("cp.async.wait_group 1;\n"); }
__device__ __forceinline__ void cp_wait0() { asm volatile("cp.async.wait_group 0;\n"); }

__device__ __forceinline__ unsigned packf16(float lo, float hi) {
    unsigned u;
    asm("cvt.rn.f16x2.f32 %0, %1, %2;" : "=r"(u) : "f"(hi), "f"(lo));
    return u;
}
__device__ __forceinline__ unsigned u4c(const uint4& v, int c) {
    return c == 0 ? v.x : (c == 1 ? v.y : (c == 2 ? v.z : v.w));
}

// ---------------------------------------------------------------------------
// m64 x n32 x k64 warp-tile (GEMM), bf16 hi/lo split, stride 36 words.
// ---------------------------------------------------------------------------
__device__ __forceinline__ void mma_tile64(unsigned sb, int AH, int AL,
                                           int BHo, int BLo, int arow, int bcol,
                                           int lane, float c[16][4]) {
    const int m = lane >> 3, r = lane & 7;
    const unsigned paw = (unsigned)((arow + (m & 1) * 8 + r) * 36 + (m >> 1) * 4) * 4;
    const unsigned pbw = (unsigned)((bcol + (m >> 1) * 8 + r) * 36 + (m & 1) * 4) * 4;
#pragma unroll
    for (int ks = 0; ks < 4; ks++) {
        unsigned ah[4][4], al_[4][4];
#pragma unroll
        for (int mt = 0; mt < 4; mt++) {
            ldsm4(sb + AH * 4 + paw + mt * (16 * 36 * 4) + ks * 32,
                  ah[mt][0], ah[mt][1], ah[mt][2], ah[mt][3]);
            ldsm4(sb + AL * 4 + paw + mt * (16 * 36 * 4) + ks * 32,
                  al_[mt][0], al_[mt][1], al_[mt][2], al_[mt][3]);
        }
#pragma unroll
        for (int np = 0; np < 2; np++) {
            unsigned bh[4], bl[4];
            ldsm4(sb + BHo * 4 + pbw + np * (16 * 36 * 4) + ks * 32,
                  bh[0], bh[1], bh[2], bh[3]);
            ldsm4(sb + BLo * 4 + pbw + np * (16 * 36 * 4) + ks * 32,
                  bl[0], bl[1], bl[2], bl[3]);
#pragma unroll
            for (int mt = 0; mt < 4; mt++) {
                float* c0 = c[mt * 4 + np * 2 + 0];
                float* c1 = c[mt * 4 + np * 2 + 1];
                mma16816(c0, ah[mt][0], ah[mt][1], ah[mt][2], ah[mt][3], bh[0], bh[1]);
                mma16816(c0, ah[mt][0], ah[mt][1], ah[mt][2], ah[mt][3], bl[0], bl[1]);
                mma16816(c0, al_[mt][0], al_[mt][1], al_[mt][2], al_[mt][3], bh[0], bh[1]);
                mma16816(c1, ah[mt][0], ah[mt][1], ah[mt][2], ah[mt][3], bh[2], bh[3]);
                mma16816(c1, ah[mt][0], ah[mt][1], ah[mt][2], ah[mt][3], bl[2], bl[3]);
                mma16816(c1, al_[mt][0], al_[mt][1], al_[mt][2], al_[mt][3], bh[2], bh[3]);
            }
        }
    }
}

// m64 x n32 x k64 warp-tile, single fp16 (q/k projection).
__device__ __forceinline__ void mma_tile64_h(unsigned sb, int A, int Bo,
                                             int arow, int bcol, int lane,
                                             float c[16][4]) {
    const int m = lane >> 3, r = lane & 7;
    const unsigned paw = (unsigned)((arow + (m & 1) * 8 + r) * 36 + (m >> 1) * 4) * 4;
    const unsigned pbw = (unsigned)((bcol + (m >> 1) * 8 + r) * 36 + (m & 1) * 4) * 4;
#pragma unroll
    for (int ks = 0; ks < 4; ks++) {
        unsigned a[4][4];
#pragma unroll
        for (int mt = 0; mt < 4; mt++)
            ldsm4(sb + A * 4 + paw + mt * (16 * 36 * 4) + ks * 32,
                  a[mt][0], a[mt][1], a[mt][2], a[mt][3]);
#pragma unroll
        for (int np = 0; np < 2; np++) {
            unsigned b0, b1, b2, b3;
            ldsm4(sb + Bo * 4 + pbw + np * (16 * 36 * 4) + ks * 32, b0, b1, b2, b3);
#pragma unroll
            for (int mt = 0; mt < 4; mt++) {
                mma16816h(c[mt * 4 + np * 2 + 0], a[mt][0], a[mt][1], a[mt][2],
                          a[mt][3], b0, b1);
                mma16816h(c[mt * 4 + np * 2 + 1], a[mt][0], a[mt][1], a[mt][2],
                          a[mt][3], b2, b3);
            }
        }
    }
}

// m16 x n64 x k64 warp-tile, single fp16 A and B (attention).
__device__ __forceinline__ void mma_tile_h(unsigned sb, int A, int Bo,
                                           int arow, int lane, float c[8][4]) {
    const int m = lane >> 3, r = lane & 7;
    const unsigned pa = ((unsigned)(arow + (m & 1) * 8 + r) * 36 + (m >> 1) * 4) * 4;
    const unsigned pb = (((unsigned)((m >> 1) * 8 + r)) * 36 + (m & 1) * 4) * 4;
#pragma unroll
    for (int ks = 0; ks < 4; ks++) {
        unsigned a0, a1, a2, a3;
        ldsm4(sb + A * 4 + pa + ks * 32, a0, a1, a2, a3);
#pragma unroll
        for (int ntp = 0; ntp < 4; ntp++) {
            unsigned b0, b1, b2, b3;
            ldsm4(sb + Bo * 4 + pb + ntp * (16 * 36 * 4) + ks * 32, b0, b1, b2, b3);
            mma16816h(c[2 * ntp + 0], a0, a1, a2, a3, b0, b1);
            mma16816h(c[2 * ntp + 1], a0, a1, a2, a3, b2, b3);
        }
    }
}

// ---------------- preprocess ----------------
__global__ __launch_bounds__(256) void split_f32(const float* __restrict__ src,
                                                 __nv_bfloat16* __restrict__ dh,
                                                 __nv_bfloat16* __restrict__ dl,
                                                 __half* __restrict__ d16, int n2) {
    int i = blockIdx.x * 256 + threadIdx.x;
    if (i < n2) {
        float2 v = reinterpret_cast<const float2*>(src)[i];
        unsigned hi, lo; split2(v.x, v.y, hi, lo);
        reinterpret_cast<unsigned*>(dh)[i] = hi;
        reinterpret_cast<unsigned*>(dl)[i] = lo;
        reinterpret_cast<unsigned*>(d16)[i] = packf16(v.x, v.y);
    }
}

__global__ __launch_bounds__(256) void tsplit_w(const float* __restrict__ W,
                                                __nv_bfloat16* __restrict__ dh,
                                                __nv_bfloat16* __restrict__ dl,
                                                __half* __restrict__ d16,
                                                int K, int NB) {
    __shared__ float tile[32][33];
    const int n0 = blockIdx.x * 32, k0 = blockIdx.y * 32;
    const int tx = threadIdx.x & 31, ty = threadIdx.x >> 5;
    for (int r = ty; r < 32; r += 8)
        tile[r][tx] = W[(size_t)(k0 + r) * NB + n0 + tx];
    __syncthreads();
    for (int u = threadIdx.x; u < 512; u += 256) {
        const int rr = u >> 4, c = (u & 15) * 2;
        unsigned hi, lo; split2(tile[c][rr], tile[c + 1][rr], hi, lo);
        const size_t off = ((size_t)(n0 + rr) * K + k0 + c) >> 1;
        reinterpret_cast<unsigned*>(dh)[off] = hi;
        reinterpret_cast<unsigned*>(dl)[off] = lo;
        if (d16)
            reinterpret_cast<unsigned*>(d16)[off] =
                packf16(tile[c][rr], tile[c + 1][rr]);
    }
}

// mask -> 2-bit packed, 16 vals per u32
__global__ __launch_bounds__(256) void pack_mask(const int* __restrict__ mask,
                                                 unsigned* __restrict__ mp, int n) {
    int i = blockIdx.x * 256 + threadIdx.x;
    if (i < n) {
        const int4* s = reinterpret_cast<const int4*>(mask) + (size_t)i * 4;
        unsigned p = 0;
#pragma unroll
        for (int q = 0; q < 4; q++) {
            int4 v = s[q];
            p |= (unsigned)(v.x & 3) << (q * 8 + 0);
            p |= (unsigned)(v.y & 3) << (q * 8 + 2);
            p |= (unsigned)(v.z & 3) << (q * 8 + 4);
            p |= (unsigned)(v.w & 3) << (q * 8 + 6);
        }
        mp[i] = p;
    }
}

// ---------------- bf16 3-product GEMM (v + out-proj) ----------------
#define SAH 0
#define SAL 4608
#define SBH 9216
#define SBL 11520
#define GSTG 13824

__global__ __launch_bounds__(128, 2) void mma_gemm(
    const __nv_bfloat16* __restrict__ Ah, const __nv_bfloat16* __restrict__ Al,
    const __nv_bfloat16* __restrict__ Bh, const __nv_bfloat16* __restrict__ Bl,
    float* __restrict__ Cout, int mode, int nbase) {
    extern __shared__ unsigned su[];
    const unsigned sbase = (unsigned)__cvta_generic_to_shared(su);
    const int K = 1024;
    const int m0 = blockIdx.y * 128, n0 = nbase + blockIdx.x * 64;
    const int tid = threadIdx.x, lane = tid & 31, wp = tid >> 5;
    const int g = lane >> 2, t = lane & 3;
    const int rg = (wp >> 1) * 64, cg = wp & 1;

    const uint4* pAh = reinterpret_cast<const uint4*>(Ah + (size_t)m0 * K);
    const uint4* pAl = reinterpret_cast<const uint4*>(Al + (size_t)m0 * K);
    const uint4* pBh = reinterpret_cast<const uint4*>(Bh + (size_t)n0 * K);
    const uint4* pBl = reinterpret_cast<const uint4*>(Bl + (size_t)n0 * K);

    float c16[16][4] = {};

#define GLOAD(ST, K0)                                                          \
    {                                                                          \
        const int kc = (K0) >> 3;                                              \
        const unsigned base = sbase + (ST) * (GSTG * 4);                       \
        for (int idx = tid; idx < 2048; idx += 128) {                          \
            const int half = idx >> 10, r = (idx & 1023) >> 3, c = idx & 7;    \
            cpa16(base + (half ? SAL : SAH) * 4 + (r * 9 + c) * 16,            \
                  (half ? pAl : pAh) + (size_t)r * 128 + kc + c);              \
        }                                                                      \
        for (int idx = tid; idx < 1024; idx += 128) {                          \
            const int half = idx >> 9, r = (idx & 511) >> 3, c = idx & 7;      \
            cpa16(base + (half ? SBL : SBH) * 4 + (r * 9 + c) * 16,            \
                  (half ? pBl : pBh) + (size_t)r * 128 + kc + c);              \
        }                                                                      \
        cp_commit();                                                           \
    }

    GLOAD(0, 0)
    for (int it = 0; it < 16; it++) {
        if (it + 1 < 16) { GLOAD((it + 1) & 1, (it + 1) * 64) cp_wait1(); }
        else cp_wait0();
        __syncthreads();
        mma_tile64(sbase + (it & 1) * (GSTG * 4), SAH, SAL, SBH, SBL,
                   rg, cg * 32, lane, c16);
        __syncthreads();
    }
#undef GLOAD

    if (mode == 0) {
        // v only: [bh][d][n] fp16
        const int b = m0 >> 11;
        const int mloc = m0 & (N_ - 1);
        const int hh = (n0 & 1023) >> 6;
        const int bh = b * H_ + hh;
#pragma unroll
        for (int mt = 0; mt < 4; mt++)
#pragma unroll
            for (int nt = 0; nt < 4; nt++) {
                const float* cc = c16[mt * 4 + nt];
                const int i0v = mloc + rg + mt * 16 + g;
                const int d = cg * 32 + nt * 8 + 2 * t;
                const size_t b0 = ((size_t)bh * D_ + d) * N_;
                const size_t b1 = ((size_t)bh * D_ + d + 1) * N_;
                g_v[b0 + i0v] = __float2half(cc[0]);
                g_v[b1 + i0v] = __float2half(cc[1]);
                g_v[b0 + i0v + 8] = __float2half(cc[2]);
                g_v[b1 + i0v + 8] = __float2half(cc[3]);
            }
    } else {
#pragma unroll
        for (int mt = 0; mt < 4; mt++)
#pragma unroll
            for (int nt = 0; nt < 4; nt++) {
                const float* cc = c16[mt * 4 + nt];
                const int R0 = m0 + rg + mt * 16 + g;
                const int n = n0 + cg * 32 + nt * 8 + 2 * t;
                *reinterpret_cast<float2*>(&Cout[(size_t)R0 * DIM_ + n]) =
                    make_float2(cc[0], cc[1]);
                *reinterpret_cast<float2*>(&Cout[(size_t)(R0 + 8) * DIM_ + n]) =
                    make_float2(cc[2], cc[3]);
            }
    }
}

// ---------------- fp16 single-product GEMM (q/k projection) ----------------
// stage: A 4608 w, B 2304 w -> 6912 w; 2 stages = 55296 B
#define HA 0
#define HB 4608
#define HSTG 6912

__global__ __launch_bounds__(128, 3) void mma_gemm_h(
    const __half* __restrict__ A16, const __half* __restrict__ B16) {
    extern __shared__ unsigned su[];
    const unsigned sbase = (unsigned)__cvta_generic_to_shared(su);
    const int K = 1024;
    const int m0 = blockIdx.y * 128, n0 = blockIdx.x * 64;
    const int tid = threadIdx.x, lane = tid & 31, wp = tid >> 5;
    const int g = lane >> 2, t = lane & 3;
    const int rg = (wp >> 1) * 64, cg = wp & 1;

    const uint4* pA = reinterpret_cast<const uint4*>(A16 + (size_t)m0 * K);
    const uint4* pB = reinterpret_cast<const uint4*>(B16 + (size_t)n0 * K);

    float c16[16][4] = {};

#define HLOAD(ST, K0)                                                          \
    {                                                                          \
        const int kc = (K0) >> 3;                                              \
        const unsigned base = sbase + (ST) * (HSTG * 4);                       \
        for (int idx = tid; idx < 1024; idx += 128) {                          \
            const int r = idx >> 3, c = idx & 7;                               \
            cpa16(base + HA * 4 + (r * 9 + c) * 16,                            \
                  pA + (size_t)r * 128 + kc + c);                              \
        }                                                                      \
        for (int idx = tid; idx < 512; idx += 128) {                           \
            const int r = idx >> 3, c = idx & 7;                               \
            cpa16(base + HB * 4 + (r * 9 + c) * 16,                            \
                  pB + (size_t)r * 128 + kc + c);                              \
        }                                                                      \
        cp_commit();                                                           \
    }

    HLOAD(0, 0)
    for (int it = 0; it < 16; it++) {
        if (it + 1 < 16) { HLOAD((it + 1) & 1, (it + 1) * 64) cp_wait1(); }
        else cp_wait0();
        __syncthreads();
        mma_tile64_h(sbase + (it & 1) * (HSTG * 4), HA, HB, rg, cg * 32, lane, c16);
        __syncthreads();
    }
#undef HLOAD

    const int part = n0 >> 10;               // 0=q, 1=k
    const int b = m0 >> 11;
    const int mloc = m0 & (N_ - 1);
    const int hh = (n0 & 1023) >> 6;
    const int bh = b * H_ + hh;
    const float SCp = (part == 0) ? 0.03125f : 1.0f;
    unsigned* uq = reinterpret_cast<unsigned*>(part == 0 ? g_q : g_k);
#pragma unroll
    for (int mt = 0; mt < 4; mt++)
#pragma unroll
        for (int nt = 0; nt < 4; nt++) {
            const float* cc = c16[mt * 4 + nt];
            const int R0 = mloc + rg + mt * 16 + g;
            const int d = cg * 32 + nt * 8 + 2 * t;
            uq[(((size_t)bh * N_ + R0) * D_ + d) >> 1] =
                packf16(cc[0] * SCp, cc[1] * SCp);
            uq[(((size_t)bh * N_ + R0 + 8) * D_ + d) >> 1] =
                packf16(cc[2] * SCp, cc[3] * SCp);
        }
}

// ---------------- HMMA segment attention: 256 thr, 8 warps @ m16n64 ---------
// fp16 everywhere. smem words: SQ (Q/W) 0..4608; stages ASST + s*2304;
// dsh 9216 (512 f). total 9728 w = 38912 B
#define SQ   0
#define ASST 4608
#define ASDS 9216

#define ACCSEG(DS, SG, E)                                                      \
    { if ((SG) == 0) (DS)[0] += (E); else if ((SG) == 1) (DS)[1] += (E);       \
      else if ((SG) == 2) (DS)[2] += (E); else (DS)[3] += (E); }

__global__ __launch_bounds__(256, 2) void attn_mma(int dummy) {
    extern __shared__ unsigned su[];
    const unsigned sbase = (unsigned)__cvta_generic_to_shared(su);
    float* dshf = reinterpret_cast<float*>(su + ASDS);
    uint4* su4 = reinterpret_cast<uint4*>(su);

    const int b = blockIdx.z, h = blockIdx.x;
    const int i0 = blockIdx.y * 128;
    const int bh = b * H_ + h;
    const int tid = threadIdx.x;
    const int lane = tid & 31, wp = tid >> 5;
    const int g = lane >> 2, t = lane & 3;
    const int r0 = wp * 16 + g, r1 = r0 + 8;
    unsigned* eblk = g_e + (((size_t)bh * 16 + blockIdx.y) << 17);
    const uint4* mp4r0 =
        reinterpret_cast<const uint4*>(g_mp) + (size_t)(b * N_ + i0 + r0) * 32;
    const uint4* mp4r1 =
        reinterpret_cast<const uint4*>(g_mp) + (size_t)(b * N_ + i0 + r1) * 32;
    const int s0 = 4 * t;

    // load Q tile (fp16)
    {
        const uint4* gq = reinterpret_cast<const uint4*>(g_q + ((size_t)bh * N_ + i0) * D_);
        for (int idx = tid; idx < 1024; idx += 256) {
            const int r = idx >> 3, c = idx & 7;
            su4[(SQ >> 2) + r * 9 + c] = gq[idx];
        }
    }

    const uint4* gk = reinterpret_cast<const uint4*>(g_k + (size_t)bh * N_ * D_);
    const uint4* gv = reinterpret_cast<const uint4*>(g_v + (size_t)bh * D_ * N_);

#define LOADK(ST, JT)                                                          \
    {                                                                          \
        const unsigned base = sbase + (ASST + (ST) * 2304) * 4;                \
        const int jr = (JT) * 512;                                             \
        for (int idx = tid; idx < 512; idx += 256) {                           \
            const int r = idx >> 3, c = idx & 7;                               \
            cpa16(base + (r * 9 + c) * 16, gk + jr + (size_t)r * 8 + c);       \
        }                                                                      \
        cp_commit();                                                           \
    }
#define LOADV(ST, JT)                                                          \
    {                                                                          \
        const unsigned base = sbase + (ASST + (ST) * 2304) * 4;                \
        const int jc = (JT) * 8;                                               \
        for (int idx = tid; idx < 512; idx += 256) {                           \
            const int r = idx >> 3, c = idx & 7;                               \
            cpa16(base + (r * 9 + c) * 16, gv + (size_t)r * 256 + jc + c);     \
        }                                                                      \
        cp_commit();                                                           \
    }

    // ---------------- PASS 1: denominators + e store ----------------
    float ds0[4] = {0.f, 0.f, 0.f, 0.f}, ds1[4] = {0.f, 0.f, 0.f, 0.f};
    uint4 um0 = mp4r0[0], um1 = mp4r1[0];
    LOADK(0, 0)
    for (int jt = 0; jt < 32; jt++) {
        uint4 un0, un1;
        if (jt + 1 < 32) {
            LOADK((jt + 1) & 1, jt + 1)
            un0 = mp4r0[jt + 1]; un1 = mp4r1[jt + 1];
            cp_wait1();
        } else cp_wait0();
        __syncthreads();
        const int koff = ASST + (jt & 1) * 2304;
        float c8[8][4] = {};
        mma_tile_h(sbase, SQ, koff, wp * 16, lane, c8);
        __syncthreads();
        unsigned ebuf[16];
#pragma unroll
        for (int nt = 0; nt < 8; nt++) {
            const unsigned u0 = u4c(um0, nt >> 1), u1 = u4c(um1, nt >> 1);
            const int sh = s0 + ((nt & 1) << 4);
            const int ma0 = (u0 >> sh) & 3, ma1 = (u0 >> (sh + 2)) & 3;
            const int mb0 = (u1 >> sh) & 3, mb1 = (u1 >> (sh + 2)) & 3;
            const float e0 = __expf(c8[nt][0]), e1 = __expf(c8[nt][1]);
            const float e2 = __expf(c8[nt][2]), e3 = __expf(c8[nt][3]);
            ACCSEG(ds0, ma0, e0) ACCSEG(ds0, ma1, e1)
            ACCSEG(ds1, mb0, e2) ACCSEG(ds1, mb1, e3)
            ebuf[2 * nt] = packf16(e0, e1);
            ebuf[2 * nt + 1] = packf16(e2, e3);
        }
        uint4* ep = reinterpret_cast<uint4*>(
            eblk + ((size_t)jt * 8 + wp) * 512 + lane * 16);
        ep[0] = make_uint4(ebuf[0], ebuf[1], ebuf[2], ebuf[3]);
        ep[1] = make_uint4(ebuf[4], ebuf[5], ebuf[6], ebuf[7]);
        ep[2] = make_uint4(ebuf[8], ebuf[9], ebuf[10], ebuf[11]);
        ep[3] = make_uint4(ebuf[12], ebuf[13], ebuf[14], ebuf[15]);
        um0 = un0; um1 = un1;
    }
#pragma unroll
    for (int s = 0; s < 4; s++) {
        float v0 = ds0[s], v1 = ds1[s];
        v0 += __shfl_xor_sync(0xffffffffu, v0, 1);
        v0 += __shfl_xor_sync(0xffffffffu, v0, 2);
        v1 += __shfl_xor_sync(0xffffffffu, v1, 1);
        v1 += __shfl_xor_sync(0xffffffffu, v1, 2);
        if (t == 0) { dshf[r0 * 4 + s] = v0; dshf[r1 * 4 + s] = v1; }
    }
    __syncthreads();
    for (int idx = tid; idx < 512; idx += 256) {
        const float dv = dshf[idx];
        dshf[idx] = (dv == 0.0f) ? 1.0f : 1.0f / dv;
    }
    __syncthreads();

    // ---------------- PASS 2: w(fp16, in SQ) = e*invd -> O += w @ V ----------
    float o8[8][4] = {};
    um0 = mp4r0[0]; um1 = mp4r1[0];
    LOADV(0, 0)
    for (int jt = 0; jt < 32; jt++) {
        const uint4* ep = reinterpret_cast<const uint4*>(
            eblk + ((size_t)jt * 8 + wp) * 512 + lane * 16);
        const uint4 ev0 = ep[0], ev1 = ep[1], ev2 = ep[2], ev3 = ep[3];
        uint4 un0, un1;
        if (jt + 1 < 32) {
            LOADV((jt + 1) & 1, jt + 1)
            un0 = mp4r0[jt + 1]; un1 = mp4r1[jt + 1];
        }
        unsigned earr[16];
        earr[0] = ev0.x; earr[1] = ev0.y; earr[2] = ev0.z; earr[3] = ev0.w;
        earr[4] = ev1.x; earr[5] = ev1.y; earr[6] = ev1.z; earr[7] = ev1.w;
        earr[8] = ev2.x; earr[9] = ev2.y; earr[10] = ev2.z; earr[11] = ev2.w;
        earr[12] = ev3.x; earr[13] = ev3.y; earr[14] = ev3.z; earr[15] = ev3.w;
#pragma unroll
        for (int nt = 0; nt < 8; nt++) {
            const unsigned u0 = u4c(um0, nt >> 1), u1 = u4c(um1, nt >> 1);
            const int sh = s0 + ((nt & 1) << 4);
            const int ma0 = (u0 >> sh) & 3, ma1 = (u0 >> (sh + 2)) & 3;
            const int mb0 = (u1 >> sh) & 3, mb1 = (u1 >> (sh + 2)) & 3;
            const float2 eA = __half22float2(
                *reinterpret_cast<const __half2*>(&earr[2 * nt]));
            const float2 eB = __half22float2(
                *reinterpret_cast<const __half2*>(&earr[2 * nt + 1]));
            su[SQ + r0 * 36 + nt * 4 + t] =
                packf16(eA.x * dshf[r0 * 4 + ma0], eA.y * dshf[r0 * 4 + ma1]);
            su[SQ + r1 * 36 + nt * 4 + t] =
                packf16(eB.x * dshf[r1 * 4 + mb0], eB.y * dshf[r1 * 4 + mb1]);
        }
        if (jt + 1 < 32) cp_wait1(); else cp_wait0();
        __syncthreads();
        const int voff = ASST + (jt & 1) * 2304;
        mma_tile_h(sbase, SQ, voff, wp * 16, lane, o8);
        __syncthreads();
        um0 = un0; um1 = un1;
    }
#undef LOADK
#undef LOADV

    // store O as split bf16
    {
        unsigned* ah = reinterpret_cast<unsigned*>(g_ah);
        unsigned* al = reinterpret_cast<unsigned*>(g_al);
#pragma unroll
        for (int nt = 0; nt < 8; nt++) {
            const int d = h * 64 + nt * 8 + 2 * t;
            unsigned hi, lo;
            split2(o8[nt][0], o8[nt][1], hi, lo);
            const size_t o0 = ((size_t)(b * N_ + i0 + r0) * DIM_ + d) >> 1;
            ah[o0] = hi; al[o0] = lo;
            split2(o8[nt][2], o8[nt][3], hi, lo);
            const size_t o1 = ((size_t)(b * N_ + i0 + r1) * DIM_ + d) >> 1;
            ah[o1] = hi; al[o1] = lo;
        }
    }
}

// ---------------------------------------------------------------------------
extern "C" void kernel_launch(void* const* d_in, const int* in_sizes, int n_in,
                              void* d_out, int out_size) {
    const float* features = (const float*)d_in[0];
    const int*   mask     = (const int*)d_in[1];
    const float* W_qkv    = (const float*)d_in[2];
    const float* W_out    = (const float*)d_in[3];
    float* out = (float*)d_out;

    cudaFuncSetAttribute(attn_mma, cudaFuncAttributeMaxDynamicSharedMemorySize, 38912);
    cudaFuncSetAttribute(mma_gemm, cudaFuncAttributeMaxDynamicSharedMemorySize, 110592);
    cudaFuncSetAttribute(mma_gemm_h, cudaFuncAttributeMaxDynamicSharedMemorySize, 55296);

    __nv_bfloat16 *fh, *fl, *wqh, *wql, *woh, *wol, *ah, *al;
    __half *f16, *wq16;
    unsigned* mp;
    cudaGetSymbolAddress((void**)&fh, g_fh);   cudaGetSymbolAddress((void**)&fl, g_fl);
    cudaGetSymbolAddress((void**)&f16, g_f16);
    cudaGetSymbolAddress((void**)&wqh, g_wqh); cudaGetSymbolAddress((void**)&wql, g_wql);
    cudaGetSymbolAddress((void**)&wq16, g_wq16);
    cudaGetSymbolAddress((void**)&woh, g_woh); cudaGetSymbolAddress((void**)&wol, g_wol);
    cudaGetSymbolAddress((void**)&ah, g_ah);   cudaGetSymbolAddress((void**)&al, g_al);
    cudaGetSymbolAddress((void**)&mp, g_mp);

    split_f32<<<(M_ * DIM_ / 2 + 255) / 256, 256>>>(features, fh, fl, f16,
                                                    M_ * DIM_ / 2);
    tsplit_w<<<dim3(3 * DIM_ / 32, DIM_ / 32), 256>>>(W_qkv, wqh, wql, wq16,
                                                      DIM_, 3 * DIM_);
    tsplit_w<<<dim3(DIM_ / 32, DIM_ / 32), 256>>>(W_out, woh, wol, nullptr,
                                                  DIM_, DIM_);
    pack_mask<<<(B_ * N_ * N_ / 16 + 255) / 256, 256>>>(mask, mp, B_ * N_ * N_ / 16);

    // q/k projection: fp16 single product
    mma_gemm_h<<<dim3(2 * DIM_ / 64, M_ / 128), 128, 55296>>>(f16, wq16);
    // v projection: bf16 3-product
    mma_gemm<<<dim3(DIM_ / 64, M_ / 128), 128, 110592>>>(fh, fl, wqh, wql,
                                                         nullptr, 0, 2 * DIM_);
    // attention
    attn_mma<<<dim3(H_, N_ / 128, B_), 256, 38912>>>(0);
    // out projection
    mma_gemm<<<dim3(DIM_ / 64, M_ / 128), 128, 110592>>>(ah, al, woh, wol,
                                                         out, 1, 0);
}

// round 16
// speedup vs baseline: 2.4554x; 1.1169x over previous
#include <cuda_runtime.h>
#include <cuda_bf16.h>
#include <cuda_fp16.h>
#include <cstdint>

#define B_   2
#define N_   2048
#define DIM_ 1024
#define H_   16
#define D_   64
#define BH_  (B_ * H_)
#define M_   (B_ * N_)

// ---- device scratch (allocation-free rule) ----
__device__ __nv_bfloat16 g_fh[(size_t)M_ * DIM_];
__device__ __nv_bfloat16 g_fl[(size_t)M_ * DIM_];
__device__ __half        g_f16[(size_t)M_ * DIM_];
__device__ __nv_bfloat16 g_wqh[(size_t)3 * DIM_ * DIM_];
__device__ __nv_bfloat16 g_wql[(size_t)3 * DIM_ * DIM_];
__device__ __half        g_wq16[(size_t)3 * DIM_ * DIM_];
__device__ __nv_bfloat16 g_woh[(size_t)DIM_ * DIM_];
__device__ __nv_bfloat16 g_wol[(size_t)DIM_ * DIM_];
__device__ __half g_q[(size_t)BH_ * N_ * D_];         // q/32, fp16
__device__ __half g_k[(size_t)BH_ * N_ * D_];         // k, fp16
__device__ __half g_v[(size_t)BH_ * D_ * N_];         // v transposed, fp16
__device__ __nv_bfloat16 g_ah[(size_t)M_ * DIM_];
__device__ __nv_bfloat16 g_al[(size_t)M_ * DIM_];
__device__ unsigned g_mp[(size_t)B_ * N_ * N_ / 16];  // mask packed 2-bit

__device__ __forceinline__ unsigned b2u(__nv_bfloat162 v) {
    return *reinterpret_cast<unsigned*>(&v);
}
__device__ __forceinline__ void split2(float x0, float x1, unsigned& hi, unsigned& lo) {
    __nv_bfloat162 h2 = __floats2bfloat162_rn(x0, x1);
    __nv_bfloat162 l2 = __floats2bfloat162_rn(x0 - __bfloat162float(h2.x),
                                              x1 - __bfloat162float(h2.y));
    hi = b2u(h2); lo = b2u(l2);
}

__device__ __forceinline__ void mma16816(float* c, unsigned a0, unsigned a1,
                                         unsigned a2, unsigned a3,
                                         unsigned b0, unsigned b1) {
    asm("mma.sync.aligned.m16n8k16.row.col.f32.bf16.bf16.f32 "
        "{%0,%1,%2,%3},{%4,%5,%6,%7},{%8,%9},{%0,%1,%2,%3};\n"
        : "+f"(c[0]), "+f"(c[1]), "+f"(c[2]), "+f"(c[3])
        : "r"(a0), "r"(a1), "r"(a2), "r"(a3), "r"(b0), "r"(b1));
}
__device__ __forceinline__ void mma16816h(float* c, unsigned a0, unsigned a1,
                                          unsigned a2, unsigned a3,
                                          unsigned b0, unsigned b1) {
    asm("mma.sync.aligned.m16n8k16.row.col.f32.f16.f16.f32 "
        "{%0,%1,%2,%3},{%4,%5,%6,%7},{%8,%9},{%0,%1,%2,%3};\n"
        : "+f"(c[0]), "+f"(c[1]), "+f"(c[2]), "+f"(c[3])
        : "r"(a0), "r"(a1), "r"(a2), "r"(a3), "r"(b0), "r"(b1));
}

__device__ __forceinline__ void ldsm4(unsigned addr, unsigned& r0, unsigned& r1,
                                      unsigned& r2, unsigned& r3) {
    asm volatile("ldmatrix.sync.aligned.m8n8.x4.shared.b16 {%0,%1,%2,%3}, [%4];\n"
                 : "=r"(r0), "=r"(r1), "=r"(r2), "=r"(r3) : "r"(addr));
}

__device__ __forceinline__ void cpa16(unsigned dst, const void* src) {
    asm volatile("cp.async.cg.shared.global [%0], [%1], 16;\n" :: "r"(dst), "l"(src));
}
__device__ __forceinline__ void cp_commit() { asm volatile("cp.async.commit_group;\n"); }
__device__ __forceinline__ void cp_wait1() { asm volatile("cp.async.wait_group 1;\n"); }
__device__ __forceinline__ void cp_wait0() { asm volatile("cp.async.wait_group 0;\n"); }

__device__ __forceinline__ unsigned packf16(float lo, float hi) {
    unsigned u;
    asm("cvt.rn.f16x2.f32 %0, %1, %2;" : "=r"(u) : "f"(hi), "f"(lo));
    return u;
}
__device__ __forceinline__ unsigned u4c(const uint4& v, int c) {
    return c == 0 ? v.x : (c == 1 ? v.y : (c == 2 ? v.z : v.w));
}

// ---------------------------------------------------------------------------
// m64 x n32 x k64 warp-tile (GEMM), bf16 hi/lo split, stride 36 words.
// ---------------------------------------------------------------------------
__device__ __forceinline__ void mma_tile64(unsigned sb, int AH, int AL,
                                           int BHo, int BLo, int arow, int bcol,
                                           int lane, float c[16][4]) {
    const int m = lane >> 3, r = lane & 7;
    const unsigned paw = (unsigned)((arow + (m & 1) * 8 + r) * 36 + (m >> 1) * 4) * 4;
    const unsigned pbw = (unsigned)((bcol + (m >> 1) * 8 + r) * 36 + (m & 1) * 4) * 4;
#pragma unroll
    for (int ks = 0; ks < 4; ks++) {
        unsigned ah[4][4], al_[4][4];
#pragma unroll
        for (int mt = 0; mt < 4; mt++) {
            ldsm4(sb + AH * 4 + paw + mt * (16 * 36 * 4) + ks * 32,
                  ah[mt][0], ah[mt][1], ah[mt][2], ah[mt][3]);
            ldsm4(sb + AL * 4 + paw + mt * (16 * 36 * 4) + ks * 32,
                  al_[mt][0], al_[mt][1], al_[mt][2], al_[mt][3]);
        }
#pragma unroll
        for (int np = 0; np < 2; np++) {
            unsigned bh[4], bl[4];
            ldsm4(sb + BHo * 4 + pbw + np * (16 * 36 * 4) + ks * 32,
                  bh[0], bh[1], bh[2], bh[3]);
            ldsm4(sb + BLo * 4 + pbw + np * (16 * 36 * 4) + ks * 32,
                  bl[0], bl[1], bl[2], bl[3]);
#pragma unroll
            for (int mt = 0; mt < 4; mt++) {
                float* c0 = c[mt * 4 + np * 2 + 0];
                float* c1 = c[mt * 4 + np * 2 + 1];
                mma16816(c0, ah[mt][0], ah[mt][1], ah[mt][2], ah[mt][3], bh[0], bh[1]);
                mma16816(c0, ah[mt][0], ah[mt][1], ah[mt][2], ah[mt][3], bl[0], bl[1]);
                mma16816(c0, al_[mt][0], al_[mt][1], al_[mt][2], al_[mt][3], bh[0], bh[1]);
                mma16816(c1, ah[mt][0], ah[mt][1], ah[mt][2], ah[mt][3], bh[2], bh[3]);
                mma16816(c1, ah[mt][0], ah[mt][1], ah[mt][2], ah[mt][3], bl[2], bl[3]);
                mma16816(c1, al_[mt][0], al_[mt][1], al_[mt][2], al_[mt][3], bh[2], bh[3]);
            }
        }
    }
}

// m64 x n32 x k64 warp-tile, single fp16 (q/k projection).
__device__ __forceinline__ void mma_tile64_h(unsigned sb, int A, int Bo,
                                             int arow, int bcol, int lane,
                                             float c[16][4]) {
    const int m = lane >> 3, r = lane & 7;
    const unsigned paw = (unsigned)((arow + (m & 1) * 8 + r) * 36 + (m >> 1) * 4) * 4;
    const unsigned pbw = (unsigned)((bcol + (m >> 1) * 8 + r) * 36 + (m & 1) * 4) * 4;
#pragma unroll
    for (int ks = 0; ks < 4; ks++) {
        unsigned a[4][4];
#pragma unroll
        for (int mt = 0; mt < 4; mt++)
            ldsm4(sb + A * 4 + paw + mt * (16 * 36 * 4) + ks * 32,
                  a[mt][0], a[mt][1], a[mt][2], a[mt][3]);
#pragma unroll
        for (int np = 0; np < 2; np++) {
            unsigned b0, b1, b2, b3;
            ldsm4(sb + Bo * 4 + pbw + np * (16 * 36 * 4) + ks * 32, b0, b1, b2, b3);
#pragma unroll
            for (int mt = 0; mt < 4; mt++) {
                mma16816h(c[mt * 4 + np * 2 + 0], a[mt][0], a[mt][1], a[mt][2],
                          a[mt][3], b0, b1);
                mma16816h(c[mt * 4 + np * 2 + 1], a[mt][0], a[mt][1], a[mt][2],
                          a[mt][3], b2, b3);
            }
        }
    }
}

// m16 x n64 x k64 warp-tile, single fp16 A and B (attention).
__device__ __forceinline__ void mma_tile_h(unsigned sb, int A, int Bo,
                                           int arow, int lane, float c[8][4]) {
    const int m = lane >> 3, r = lane & 7;
    const unsigned pa = ((unsigned)(arow + (m & 1) * 8 + r) * 36 + (m >> 1) * 4) * 4;
    const unsigned pb = (((unsigned)((m >> 1) * 8 + r)) * 36 + (m & 1) * 4) * 4;
#pragma unroll
    for (int ks = 0; ks < 4; ks++) {
        unsigned a0, a1, a2, a3;
        ldsm4(sb + A * 4 + pa + ks * 32, a0, a1, a2, a3);
#pragma unroll
        for (int ntp = 0; ntp < 4; ntp++) {
            unsigned b0, b1, b2, b3;
            ldsm4(sb + Bo * 4 + pb + ntp * (16 * 36 * 4) + ks * 32, b0, b1, b2, b3);
            mma16816h(c[2 * ntp + 0], a0, a1, a2, a3, b0, b1);
            mma16816h(c[2 * ntp + 1], a0, a1, a2, a3, b2, b3);
        }
    }
}

// ---------------- preprocess ----------------
__global__ __launch_bounds__(256) void split_f32(const float* __restrict__ src,
                                                 __nv_bfloat16* __restrict__ dh,
                                                 __nv_bfloat16* __restrict__ dl,
                                                 __half* __restrict__ d16, int n2) {
    int i = blockIdx.x * 256 + threadIdx.x;
    if (i < n2) {
        float2 v = reinterpret_cast<const float2*>(src)[i];
        unsigned hi, lo; split2(v.x, v.y, hi, lo);
        reinterpret_cast<unsigned*>(dh)[i] = hi;
        reinterpret_cast<unsigned*>(dl)[i] = lo;
        reinterpret_cast<unsigned*>(d16)[i] = packf16(v.x, v.y);
    }
}

__global__ __launch_bounds__(256) void tsplit_w(const float* __restrict__ W,
                                                __nv_bfloat16* __restrict__ dh,
                                                __nv_bfloat16* __restrict__ dl,
                                                __half* __restrict__ d16,
                                                int K, int NB) {
    __shared__ float tile[32][33];
    const int n0 = blockIdx.x * 32, k0 = blockIdx.y * 32;
    const int tx = threadIdx.x & 31, ty = threadIdx.x >> 5;
    for (int r = ty; r < 32; r += 8)
        tile[r][tx] = W[(size_t)(k0 + r) * NB + n0 + tx];
    __syncthreads();
    for (int u = threadIdx.x; u < 512; u += 256) {
        const int rr = u >> 4, c = (u & 15) * 2;
        unsigned hi, lo; split2(tile[c][rr], tile[c + 1][rr], hi, lo);
        const size_t off = ((size_t)(n0 + rr) * K + k0 + c) >> 1;
        reinterpret_cast<unsigned*>(dh)[off] = hi;
        reinterpret_cast<unsigned*>(dl)[off] = lo;
        if (d16)
            reinterpret_cast<unsigned*>(d16)[off] =
                packf16(tile[c][rr], tile[c + 1][rr]);
    }
}

__global__ __launch_bounds__(256) void pack_mask(const int* __restrict__ mask,
                                                 unsigned* __restrict__ mp, int n) {
    int i = blockIdx.x * 256 + threadIdx.x;
    if (i < n) {
        const int4* s = reinterpret_cast<const int4*>(mask) + (size_t)i * 4;
        unsigned p = 0;
#pragma unroll
        for (int q = 0; q < 4; q++) {
            int4 v = s[q];
            p |= (unsigned)(v.x & 3) << (q * 8 + 0);
            p |= (unsigned)(v.y & 3) << (q * 8 + 2);
            p |= (unsigned)(v.z & 3) << (q * 8 + 4);
            p |= (unsigned)(v.w & 3) << (q * 8 + 6);
        }
        mp[i] = p;
    }
}

// ---------------- bf16 3-product GEMM (v + out-proj) ----------------
#define SAH 0
#define SAL 4608
#define SBH 9216
#define SBL 11520
#define GSTG 13824

__global__ __launch_bounds__(128, 2) void mma_gemm(
    const __nv_bfloat16* __restrict__ Ah, const __nv_bfloat16* __restrict__ Al,
    const __nv_bfloat16* __restrict__ Bh, const __nv_bfloat16* __restrict__ Bl,
    float* __restrict__ Cout, int mode, int nbase) {
    extern __shared__ unsigned su[];
    const unsigned sbase = (unsigned)__cvta_generic_to_shared(su);
    const int K = 1024;
    const int m0 = blockIdx.y * 128, n0 = nbase + blockIdx.x * 64;
    const int tid = threadIdx.x, lane = tid & 31, wp = tid >> 5;
    const int g = lane >> 2, t = lane & 3;
    const int rg = (wp >> 1) * 64, cg = wp & 1;

    const uint4* pAh = reinterpret_cast<const uint4*>(Ah + (size_t)m0 * K);
    const uint4* pAl = reinterpret_cast<const uint4*>(Al + (size_t)m0 * K);
    const uint4* pBh = reinterpret_cast<const uint4*>(Bh + (size_t)n0 * K);
    const uint4* pBl = reinterpret_cast<const uint4*>(Bl + (size_t)n0 * K);

    float c16[16][4] = {};

#define GLOAD(ST, K0)                                                          \
    {                                                                          \
        const int kc = (K0) >> 3;                                              \
        const unsigned base = sbase + (ST) * (GSTG * 4);                       \
        for (int idx = tid; idx < 2048; idx += 128) {                          \
            const int half = idx >> 10, r = (idx & 1023) >> 3, c = idx & 7;    \
            cpa16(base + (half ? SAL : SAH) * 4 + (r * 9 + c) * 16,            \
                  (half ? pAl : pAh) + (size_t)r * 128 + kc + c);              \
        }                                                                      \
        for (int idx = tid; idx < 1024; idx += 128) {                          \
            const int half = idx >> 9, r = (idx & 511) >> 3, c = idx & 7;      \
            cpa16(base + (half ? SBL : SBH) * 4 + (r * 9 + c) * 16,            \
                  (half ? pBl : pBh) + (size_t)r * 128 + kc + c);              \
        }                                                                      \
        cp_commit();                                                           \
    }

    GLOAD(0, 0)
    for (int it = 0; it < 16; it++) {
        if (it + 1 < 16) { GLOAD((it + 1) & 1, (it + 1) * 64) cp_wait1(); }
        else cp_wait0();
        __syncthreads();
        mma_tile64(sbase + (it & 1) * (GSTG * 4), SAH, SAL, SBH, SBL,
                   rg, cg * 32, lane, c16);
        __syncthreads();
    }
#undef GLOAD

    if (mode == 0) {
        const int b = m0 >> 11;
        const int mloc = m0 & (N_ - 1);
        const int hh = (n0 & 1023) >> 6;
        const int bh = b * H_ + hh;
#pragma unroll
        for (int mt = 0; mt < 4; mt++)
#pragma unroll
            for (int nt = 0; nt < 4; nt++) {
                const float* cc = c16[mt * 4 + nt];
                const int i0v = mloc + rg + mt * 16 + g;
                const int d = cg * 32 + nt * 8 + 2 * t;
                const size_t b0 = ((size_t)bh * D_ + d) * N_;
                const size_t b1 = ((size_t)bh * D_ + d + 1) * N_;
                g_v[b0 + i0v] = __float2half(cc[0]);
                g_v[b1 + i0v] = __float2half(cc[1]);
                g_v[b0 + i0v + 8] = __float2half(cc[2]);
                g_v[b1 + i0v + 8] = __float2half(cc[3]);
            }
    } else {
#pragma unroll
        for (int mt = 0; mt < 4; mt++)
#pragma unroll
            for (int nt = 0; nt < 4; nt++) {
                const float* cc = c16[mt * 4 + nt];
                const int R0 = m0 + rg + mt * 16 + g;
                const int n = n0 + cg * 32 + nt * 8 + 2 * t;
                *reinterpret_cast<float2*>(&Cout[(size_t)R0 * DIM_ + n]) =
                    make_float2(cc[0], cc[1]);
                *reinterpret_cast<float2*>(&Cout[(size_t)(R0 + 8) * DIM_ + n]) =
                    make_float2(cc[2], cc[3]);
            }
    }
}

// ---------------- fp16 single-product GEMM (q/k projection) ----------------
#define HA 0
#define HB 4608
#define HSTG 6912

__global__ __launch_bounds__(128, 3) void mma_gemm_h(
    const __half* __restrict__ A16, const __half* __restrict__ B16) {
    extern __shared__ unsigned su[];
    const unsigned sbase = (unsigned)__cvta_generic_to_shared(su);
    const int K = 1024;
    const int m0 = blockIdx.y * 128, n0 = blockIdx.x * 64;
    const int tid = threadIdx.x, lane = tid & 31, wp = tid >> 5;
    const int g = lane >> 2, t = lane & 3;
    const int rg = (wp >> 1) * 64, cg = wp & 1;

    const uint4* pA = reinterpret_cast<const uint4*>(A16 + (size_t)m0 * K);
    const uint4* pB = reinterpret_cast<const uint4*>(B16 + (size_t)n0 * K);

    float c16[16][4] = {};

#define HLOAD(ST, K0)                                                          \
    {                                                                          \
        const int kc = (K0) >> 3;                                              \
        const unsigned base = sbase + (ST) * (HSTG * 4);                       \
        for (int idx = tid; idx < 1024; idx += 128) {                          \
            const int r = idx >> 3, c = idx & 7;                               \
            cpa16(base + HA * 4 + (r * 9 + c) * 16,                            \
                  pA + (size_t)r * 128 + kc + c);                              \
        }                                                                      \
        for (int idx = tid; idx < 512; idx += 128) {                           \
            const int r = idx >> 3, c = idx & 7;                               \
            cpa16(base + HB * 4 + (r * 9 + c) * 16,                            \
                  pB + (size_t)r * 128 + kc + c);                              \
        }                                                                      \
        cp_commit();                                                           \
    }

    HLOAD(0, 0)
    for (int it = 0; it < 16; it++) {
        if (it + 1 < 16) { HLOAD((it + 1) & 1, (it + 1) * 64) cp_wait1(); }
        else cp_wait0();
        __syncthreads();
        mma_tile64_h(sbase + (it & 1) * (HSTG * 4), HA, HB, rg, cg * 32, lane, c16);
        __syncthreads();
    }
#undef HLOAD

    const int part = n0 >> 10;
    const int b = m0 >> 11;
    const int mloc = m0 & (N_ - 1);
    const int hh = (n0 & 1023) >> 6;
    const int bh = b * H_ + hh;
    const float SCp = (part == 0) ? 0.03125f : 1.0f;
    unsigned* uq = reinterpret_cast<unsigned*>(part == 0 ? g_q : g_k);
#pragma unroll
    for (int mt = 0; mt < 4; mt++)
#pragma unroll
        for (int nt = 0; nt < 4; nt++) {
            const float* cc = c16[mt * 4 + nt];
            const int R0 = mloc + rg + mt * 16 + g;
            const int d = cg * 32 + nt * 8 + 2 * t;
            uq[(((size_t)bh * N_ + R0) * D_ + d) >> 1] =
                packf16(cc[0] * SCp, cc[1] * SCp);
            uq[(((size_t)bh * N_ + R0 + 8) * D_ + d) >> 1] =
                packf16(cc[2] * SCp, cc[3] * SCp);
        }
}

// ---------------- HMMA segment attention, e recomputed (no gmem e) ---------
// smem words: SQ 0 (4608), SW 4608 (4608), stages ASST + s*4608 (K +0, V +2304);
// dsh 18432 (512 f). total 18944 w = 75776 B -> 2 blocks/SM.
#define SQ   0
#define SW   4608
#define ASST 9216
#define ASDS 18432

#define ACCSEG(DS, SG, E)                                                      \
    { if ((SG) == 0) (DS)[0] += (E); else if ((SG) == 1) (DS)[1] += (E);       \
      else if ((SG) == 2) (DS)[2] += (E); else (DS)[3] += (E); }

__global__ __launch_bounds__(256, 2) void attn_mma(int dummy) {
    extern __shared__ unsigned su[];
    const unsigned sbase = (unsigned)__cvta_generic_to_shared(su);
    float* dshf = reinterpret_cast<float*>(su + ASDS);
    uint4* su4 = reinterpret_cast<uint4*>(su);

    const int b = blockIdx.z, h = blockIdx.x;
    const int i0 = blockIdx.y * 128;
    const int bh = b * H_ + h;
    const int tid = threadIdx.x;
    const int lane = tid & 31, wp = tid >> 5;
    const int g = lane >> 2, t = lane & 3;
    const int r0 = wp * 16 + g, r1 = r0 + 8;
    const uint4* mp4r0 =
        reinterpret_cast<const uint4*>(g_mp) + (size_t)(b * N_ + i0 + r0) * 32;
    const uint4* mp4r1 =
        reinterpret_cast<const uint4*>(g_mp) + (size_t)(b * N_ + i0 + r1) * 32;
    const int s0 = 4 * t;

    // load Q tile (fp16)
    {
        const uint4* gq = reinterpret_cast<const uint4*>(g_q + ((size_t)bh * N_ + i0) * D_);
        for (int idx = tid; idx < 1024; idx += 256) {
            const int r = idx >> 3, c = idx & 7;
            su4[(SQ >> 2) + r * 9 + c] = gq[idx];
        }
    }

    const uint4* gk = reinterpret_cast<const uint4*>(g_k + (size_t)bh * N_ * D_);
    const uint4* gv = reinterpret_cast<const uint4*>(g_v + (size_t)bh * D_ * N_);

#define LOADK(ST, JT)                                                          \
    {                                                                          \
        const unsigned base = sbase + (ASST + (ST) * 4608) * 4;                \
        const int jr = (JT) * 512;                                             \
        for (int idx = tid; idx < 512; idx += 256) {                           \
            const int r = idx >> 3, c = idx & 7;                               \
            cpa16(base + (r * 9 + c) * 16, gk + jr + (size_t)r * 8 + c);       \
        }                                                                      \
        cp_commit();                                                           \
    }
#define LOADKV(ST, JT)                                                         \
    {                                                                          \
        const unsigned base = sbase + (ASST + (ST) * 4608) * 4;                \
        const int jr = (JT) * 512;                                             \
        const int jc = (JT) * 8;                                               \
        for (int idx = tid; idx < 512; idx += 256) {                           \
            const int r = idx >> 3, c = idx & 7;                               \
            cpa16(base + (r * 9 + c) * 16, gk + jr + (size_t)r * 8 + c);       \
        }                                                                      \
        for (int idx = tid; idx < 512; idx += 256) {                           \
            const int r = idx >> 3, c = idx & 7;                               \
            cpa16(base + 9216 + (r * 9 + c) * 16, gv + (size_t)r * 256 + jc + c); \
        }                                                                      \
        cp_commit();                                                           \
    }

    // ---------------- PASS 1: denominators only ----------------
    float ds0[4] = {0.f, 0.f, 0.f, 0.f}, ds1[4] = {0.f, 0.f, 0.f, 0.f};
    uint4 um0 = mp4r0[0], um1 = mp4r1[0];
    LOADK(0, 0)
    for (int jt = 0; jt < 32; jt++) {
        uint4 un0, un1;
        if (jt + 1 < 32) {
            LOADK((jt + 1) & 1, jt + 1)
            un0 = mp4r0[jt + 1]; un1 = mp4r1[jt + 1];
            cp_wait1();
        } else cp_wait0();
        __syncthreads();
        const int koff = ASST + (jt & 1) * 4608;
        float c8[8][4] = {};
        mma_tile_h(sbase, SQ, koff, wp * 16, lane, c8);
        __syncthreads();
#pragma unroll
        for (int nt = 0; nt < 8; nt++) {
            const unsigned u0 = u4c(um0, nt >> 1), u1 = u4c(um1, nt >> 1);
            const int sh = s0 + ((nt & 1) << 4);
            const int ma0 = (u0 >> sh) & 3, ma1 = (u0 >> (sh + 2)) & 3;
            const int mb0 = (u1 >> sh) & 3, mb1 = (u1 >> (sh + 2)) & 3;
            const float e0 = __expf(c8[nt][0]), e1 = __expf(c8[nt][1]);
            const float e2 = __expf(c8[nt][2]), e3 = __expf(c8[nt][3]);
            ACCSEG(ds0, ma0, e0) ACCSEG(ds0, ma1, e1)
            ACCSEG(ds1, mb0, e2) ACCSEG(ds1, mb1, e3)
        }
        um0 = un0; um1 = un1;
    }
#pragma unroll
    for (int s = 0; s < 4; s++) {
        float v0 = ds0[s], v1 = ds1[s];
        v0 += __shfl_xor_sync(0xffffffffu, v0, 1);
        v0 += __shfl_xor_sync(0xffffffffu, v0, 2);
        v1 += __shfl_xor_sync(0xffffffffu, v1, 1);
        v1 += __shfl_xor_sync(0xffffffffu, v1, 2);
        if (t == 0) { dshf[r0 * 4 + s] = v0; dshf[r1 * 4 + s] = v1; }
    }
    __syncthreads();
    for (int idx = tid; idx < 512; idx += 256) {
        const float dv = dshf[idx];
        dshf[idx] = (dv == 0.0f) ? 1.0f : 1.0f / dv;
    }
    __syncthreads();

    // ------------- PASS 2: recompute scores, w = e*inv -> O += w @ V --------
    float o8[8][4] = {};
    um0 = mp4r0[0]; um1 = mp4r1[0];
    LOADKV(0, 0)
    for (int jt = 0; jt < 32; jt++) {
        uint4 un0, un1;
        if (jt + 1 < 32) {
            LOADKV((jt + 1) & 1, jt + 1)
            un0 = mp4r0[jt + 1]; un1 = mp4r1[jt + 1];
            cp_wait1();
        } else cp_wait0();
        __syncthreads();
        const int koff = ASST + (jt & 1) * 4608;
        float c8[8][4] = {};
        mma_tile_h(sbase, SQ, koff, wp * 16, lane, c8);
#pragma unroll
        for (int nt = 0; nt < 8; nt++) {
            const unsigned u0 = u4c(um0, nt >> 1), u1 = u4c(um1, nt >> 1);
            const int sh = s0 + ((nt & 1) << 4);
            const int ma0 = (u0 >> sh) & 3, ma1 = (u0 >> (sh + 2)) & 3;
            const int mb0 = (u1 >> sh) & 3, mb1 = (u1 >> (sh + 2)) & 3;
            const float e0 = __expf(c8[nt][0]), e1 = __expf(c8[nt][1]);
            const float e2 = __expf(c8[nt][2]), e3 = __expf(c8[nt][3]);
            su[SW + r0 * 36 + nt * 4 + t] =
                packf16(e0 * dshf[r0 * 4 + ma0], e1 * dshf[r0 * 4 + ma1]);
            su[SW + r1 * 36 + nt * 4 + t] =
                packf16(e2 * dshf[r1 * 4 + mb0], e3 * dshf[r1 * 4 + mb1]);
        }
        __syncwarp();
        mma_tile_h(sbase, SW, koff + 2304, wp * 16, lane, o8);
        __syncthreads();
        um0 = un0; um1 = un1;
    }
#undef LOADK
#undef LOADKV

    // store O as split bf16
    {
        unsigned* ah = reinterpret_cast<unsigned*>(g_ah);
        unsigned* al = reinterpret_cast<unsigned*>(g_al);
#pragma unroll
        for (int nt = 0; nt < 8; nt++) {
            const int d = h * 64 + nt * 8 + 2 * t;
            unsigned hi, lo;
            split2(o8[nt][0], o8[nt][1], hi, lo);
            const size_t o0 = ((size_t)(b * N_ + i0 + r0) * DIM_ + d) >> 1;
            ah[o0] = hi; al[o0] = lo;
            split2(o8[nt][2], o8[nt][3], hi, lo);
            const size_t o1 = ((size_t)(b * N_ + i0 + r1) * DIM_ + d) >> 1;
            ah[o1] = hi; al[o1] = lo;
        }
    }
}

// ---------------------------------------------------------------------------
extern "C" void kernel_launch(void* const* d_in, const int* in_sizes, int n_in,
                              void* d_out, int out_size) {
    const float* features = (const float*)d_in[0];
    const int*   mask     = (const int*)d_in[1];
    const float* W_qkv    = (const float*)d_in[2];
    const float* W_out    = (const float*)d_in[3];
    float* out = (float*)d_out;

    cudaFuncSetAttribute(attn_mma, cudaFuncAttributeMaxDynamicSharedMemorySize, 75776);
    cudaFuncSetAttribute(mma_gemm, cudaFuncAttributeMaxDynamicSharedMemorySize, 110592);
    cudaFuncSetAttribute(mma_gemm_h, cudaFuncAttributeMaxDynamicSharedMemorySize, 55296);

    __nv_bfloat16 *fh, *fl, *wqh, *wql, *woh, *wol, *ah, *al;
    __half *f16, *wq16;
    unsigned* mp;
    cudaGetSymbolAddress((void**)&fh, g_fh);   cudaGetSymbolAddress((void**)&fl, g_fl);
    cudaGetSymbolAddress((void**)&f16, g_f16);
    cudaGetSymbolAddress((void**)&wqh, g_wqh); cudaGetSymbolAddress((void**)&wql, g_wql);
    cudaGetSymbolAddress((void**)&wq16, g_wq16);
    cudaGetSymbolAddress((void**)&woh, g_woh); cudaGetSymbolAddress((void**)&wol, g_wol);
    cudaGetSymbolAddress((void**)&ah, g_ah);   cudaGetSymbolAddress((void**)&al, g_al);
    cudaGetSymbolAddress((void**)&mp, g_mp);

    split_f32<<<(M_ * DIM_ / 2 + 255) / 256, 256>>>(features, fh, fl, f16,
                                                    M_ * DIM_ / 2);
    tsplit_w<<<dim3(3 * DIM_ / 32, DIM_ / 32), 256>>>(W_qkv, wqh, wql, wq16,
                                                      DIM_, 3 * DIM_);
    tsplit_w<<<dim3(DIM_ / 32, DIM_ / 32), 256>>>(W_out, woh, wol, nullptr,
                                                  DIM_, DIM_);
    pack_mask<<<(B_ * N_ * N_ / 16 + 255) / 256, 256>>>(mask, mp, B_ * N_ * N_ / 16);

    mma_gemm_h<<<dim3(2 * DIM_ / 64, M_ / 128), 128, 55296>>>(f16, wq16);
    mma_gemm<<<dim3(DIM_ / 64, M_ / 128), 128, 110592>>>(fh, fl, wqh, wql,
                                                         nullptr, 0, 2 * DIM_);
    attn_mma<<<dim3(H_, N_ / 128, B_), 256, 75776>>>(0);
    mma_gemm<<<dim3(DIM_ / 64, M_ / 128), 128, 110592>>>(ah, al, woh, wol,
                                                         out, 1, 0);
}